// round 7
// baseline (speedup 1.0000x reference)
#include <cuda_runtime.h>
#include <cuda_bf16.h>
#include <cstdint>

// SupConLoss: N=8192 embeddings (C=128, L2-normalized), logits = X X^T / T.
// tcgen05 bf16 hi/lo-split syrk + fused exp/mask epilogue, software-pipelined
// (TMEM/B double-buffer, epilogue deferred one tile). fp32 fallback retained.

#define Nn 8192
#define TILE 128
#define NB 64
#define TOT_TILES (NB*NB)            // 4096 128x128 tiles
#define NBLK_TC 148
#define INV_T 14.285714285714285714f
#define EX2C 20.60992915555662f      // INV_T * log2(e)

// fp32 fallback tiling
#define BM 64
#define BN 64
#define NTC_F (Nn/BN)
#define TOT_TILES_F ((Nn/BM)*(Nn/BN))
#define NBLK_F 444

// ---- does this compilation pass have tcgen05? ----
#if !defined(__CUDA_ARCH__)
#  define TC_OK 1   /* host pass */
#elif defined(__CUDA_ARCH_FEAT_SM103_ALL) || defined(__CUDA_ARCH_FEAT_SM100_ALL) || \
      defined(__CUDA_ARCH_FEAT_SM101_ALL) || defined(__CUDA_ARCH_FAMILY_SPECIFIC__) || \
      defined(__CUDA_ARCH_SPECIFIC__)
#  define TC_OK 1
#else
#  define TC_OK 0
#endif

// ---- scratch (device globals; no allocation allowed) ----
__device__ uint4 g_hi[Nn * 128 / 8];   // 2 MB blocked SW128-swizzled bf16 tiles
__device__ uint4 g_lo[Nn * 128 / 8];
__device__ float g_XT[128 * Nn];       // 4 MB k-major fp32 (fallback)
__device__ float g_S[Nn];
__device__ float g_P[Nn];
__device__ int   g_lab[Nn];
__device__ int   g_hist[4];
__device__ int   g_tc;                 // 1 iff tcgen05 path is live

// ---- PTX helpers ----
__device__ __forceinline__ uint32_t smem_u32(const void* p) {
    uint32_t a;
    asm("{ .reg .u64 t; cvta.to.shared.u64 t, %1; cvt.u32.u64 %0, t; }" : "=r"(a) : "l"(p));
    return a;
}
__device__ __forceinline__ uint32_t elect_one() {
    uint32_t pred;
    asm volatile("{ .reg .pred p; elect.sync _|p, 0xFFFFFFFF; selp.b32 %0, 1, 0, p; }" : "=r"(pred));
    return pred;
}
#define MBARRIER_INIT(mb, c) \
    asm volatile("mbarrier.init.shared.b64 [%0], %1;" :: "r"((uint32_t)(mb)), "r"((uint32_t)(c)) : "memory")
#define MBARRIER_INVAL(mb) \
    asm volatile("mbarrier.inval.shared.b64 [%0];" :: "r"((uint32_t)(mb)) : "memory")
#define MBARRIER_WAIT_PARITY(mb, ph) do {                                          \
    uint32_t _m = (uint32_t)(mb), _p = (uint32_t)(ph), _d;                         \
    asm volatile("{ .reg .pred p; mbarrier.try_wait.parity.acquire.cta.shared::cta.b64 p, [%1], %2; selp.b32 %0, 1, 0, p; }" \
                 : "=r"(_d) : "r"(_m), "r"(_p) : "memory");                        \
    if (!_d) {                                                                     \
        asm volatile("{ .reg .pred P1; WL_%=: mbarrier.try_wait.parity.acquire.cta.shared::cta.b64 P1, [%0], %1, 0x989680; @P1 bra.uni WD_%=; bra.uni WL_%=; WD_%=: }" \
                     :: "r"(_m), "r"(_p) : "memory");                              \
    } } while (0)

#if TC_OK
#define TCGEN05_ALLOC(sa, n) \
    asm volatile("tcgen05.alloc.cta_group::1.sync.aligned.shared::cta.b32 [%0], %1;" \
                 :: "r"((uint32_t)(sa)), "r"((uint32_t)(n)) : "memory")
#define TCGEN05_DEALLOC(t, n) \
    asm volatile("tcgen05.dealloc.cta_group::1.sync.aligned.b32 %0, %1;" :: "r"(t), "r"((uint32_t)(n)))
#define TCGEN05_RELINQ() \
    asm volatile("tcgen05.relinquish_alloc_permit.cta_group::1.sync.aligned;")
#define TCGEN05_COMMIT(mb) \
    asm volatile("tcgen05.commit.cta_group::1.mbarrier::arrive::one.shared::cluster.b64 [%0];" \
                 :: "r"((uint32_t)(mb)) : "memory")
#define TCGEN05_WAIT_LD()      asm volatile("tcgen05.wait::ld.sync.aligned;" ::: "memory")
#define TCGEN05_FENCE_BEFORE() asm volatile("tcgen05.fence::before_thread_sync;" ::: "memory")
#define TCGEN05_FENCE_AFTER()  asm volatile("tcgen05.fence::after_thread_sync;" ::: "memory")
#define TCGEN05_LD_X32(r, a) \
    asm volatile("tcgen05.ld.sync.aligned.32x32b.x32.b32 " \
        "{%0,%1,%2,%3,%4,%5,%6,%7,%8,%9,%10,%11,%12,%13,%14,%15," \
        "%16,%17,%18,%19,%20,%21,%22,%23,%24,%25,%26,%27,%28,%29,%30,%31}, [%32];" \
        : "=r"((r)[0]),"=r"((r)[1]),"=r"((r)[2]),"=r"((r)[3]),"=r"((r)[4]),"=r"((r)[5]),"=r"((r)[6]),"=r"((r)[7]), \
          "=r"((r)[8]),"=r"((r)[9]),"=r"((r)[10]),"=r"((r)[11]),"=r"((r)[12]),"=r"((r)[13]),"=r"((r)[14]),"=r"((r)[15]), \
          "=r"((r)[16]),"=r"((r)[17]),"=r"((r)[18]),"=r"((r)[19]),"=r"((r)[20]),"=r"((r)[21]),"=r"((r)[22]),"=r"((r)[23]), \
          "=r"((r)[24]),"=r"((r)[25]),"=r"((r)[26]),"=r"((r)[27]),"=r"((r)[28]),"=r"((r)[29]),"=r"((r)[30]),"=r"((r)[31]) \
        : "r"(a))

static constexpr uint64_t SMEM_DESC_BASE_SW128 =
    (uint64_t(2) << 61) | (uint64_t(1) << 46) | (uint64_t(64) << 32) | (uint64_t(1) << 16);
#define MAKE_DESC(addr) (SMEM_DESC_BASE_SW128 | ((uint64_t)((addr) >> 4) & 0x3FFF))

// SS cg1 bf16 MMA, fp32 accumulate. idesc: F32 d, BF16 a/b, M=128, N=128.
#define MMA_IDESC 0x08200490u
static __device__ __forceinline__ void mma_ss(uint32_t d, uint64_t a, uint64_t b, uint32_t en) {
    asm volatile("{ .reg .pred p; setp.ne.u32 p, %4, 0;\n\t"
        "tcgen05.mma.cta_group::1.kind::f16 [%0], %1, %2, %3, {%5,%5,%5,%5}, p; }"
        :: "r"(d), "l"(a), "l"(b), "r"(MMA_IDESC), "r"(en), "r"(0u) : "memory");
}
#endif  // TC_OK

// ---- smem layout (k_main_tc), bytes; tile bases 1024-aligned ----
#define OFF_AHI 0
#define OFF_ALO 32768
#define OFF_B0H 65536
#define OFF_B0L 98304
#define OFF_B1H 131072
#define OFF_B1L 163840
#define OFF_TP  196608
#define OFF_MB  196624    // 2 mbarriers
#define OFF_LAB 196640    // 2 x 512B label buffers
#define SMEM_SZ 197664

// ---- prologue kernels (arch-generic) ----
__global__ void k_probe() {
#if TC_OK
    g_tc = 1;
#else
    g_tc = 0;
#endif
}

__global__ void k_zero() {
    int i = blockIdx.x * 256 + threadIdx.x;
    if (i < Nn) { g_S[i] = 0.f; g_P[i] = 0.f; }
    if (i < 4) g_hist[i] = 0;
}

// fp32 [B=4,V=2,C=128,HW=1024] -> bf16 hi/lo in blocked SW128 tile format.
__global__ void k_prep(const float* __restrict__ f) {
    int idx = blockIdx.x * 256 + threadIdx.x;   // 524288
    int n = idx & 8191;
    int j = idx >> 13;
    int vb = n >> 10, hw = n & 1023;
    int v = vb >> 2, b = vb & 3;
    const float* base = f + b * 262144 + v * 131072 + hw;
    float x0 = base[(2 * j) * 1024];
    float x1 = base[(2 * j + 1) * 1024];
    __nv_bfloat16 h0 = __float2bfloat16(x0);
    __nv_bfloat16 h1 = __float2bfloat16(x1);
    __nv_bfloat16 l0 = __float2bfloat16(x0 - __bfloat162float(h0));
    __nv_bfloat16 l1 = __float2bfloat16(x1 - __bfloat162float(h1));
    uint32_t hp = (uint32_t)__bfloat16_as_ushort(h0) | ((uint32_t)__bfloat16_as_ushort(h1) << 16);
    uint32_t lp = (uint32_t)__bfloat16_as_ushort(l0) | ((uint32_t)__bfloat16_as_ushort(l1) << 16);
    int band = n >> 7, r = n & 127, k = 2 * j;
    int atom = (r >> 3) + (k >> 6) * 16;
    uint32_t byte = atom * 1024 + (r & 7) * 128 + (k & 63) * 2;
    uint32_t sw = byte ^ ((byte >> 3) & 0x70);  // SW128
    uint32_t w = band * 8192 + (sw >> 2);
    ((uint32_t*)g_hi)[w] = hp;
    ((uint32_t*)g_lo)[w] = lp;
}

// fp32 k-major repack; only needed by the fallback -> skip when tc is live
__global__ void k_repack(const float* __restrict__ f) {
    if (g_tc) return;
    int idx = blockIdx.x * 256 + threadIdx.x;   // 262144
    int q  = idx & 255;
    int t  = idx >> 8;
    int vb = t & 7;
    int c  = t >> 3;
    int v  = vb >> 2, b = vb & 3;
    float4 val = ((const float4*)f)[b * 65536 + v * 32768 + c * 256 + q];
    ((float4*)g_XT)[c * 2048 + vb * 256 + q] = val;
}

__global__ void k_lab(const int* __restrict__ labels) {
    int n = blockIdx.x * 256 + threadIdx.x;
    if (n >= Nn) return;
    int vb = n >> 10;
    int v = vb >> 2, b = vb & 3;
    int L = labels[b * 2048 + v * 1024 + (n & 1023)];
    g_lab[n] = L;
    atomicAdd(&g_hist[L], 1);
}

// ---- tcgen05 main: 148 persistent CTAs, 8 warps, 2-stage pipeline ----
__global__ __launch_bounds__(256, 1) __cluster_dims__(1, 1, 1) void k_main_tc() {
#if TC_OK
    extern __shared__ char smc[];
    uint32_t sb = smem_u32(smc);
    int tid = threadIdx.x, wid = tid >> 5, lid = tid & 31;

    if (wid == 0) TCGEN05_ALLOC(sb + OFF_TP, 512);
    else          TCGEN05_RELINQ();
    __syncthreads();
    uint32_t tbase;
    asm volatile("ld.shared.b32 %0, [%1];" : "=r"(tbase) : "r"(sb + OFF_TP));
    if (tid == 0) { MBARRIER_INIT(sb + OFF_MB, 1); MBARRIER_INIT(sb + OFF_MB + 8, 1); }
    __syncthreads();

    const uint32_t KOFF[8] = {0, 2, 4, 6, 1024, 1026, 1028, 1030};  // 16B units

    int t0 = (int)(((long long)blockIdx.x * TOT_TILES) / NBLK_TC);
    int t1 = (int)(((long long)(blockIdx.x + 1) * TOT_TILES) / NBLK_TC);
    int phs[2] = {0, 0};
    int curA = -1, pend = -1, prow = 0, pcol = 0;

    int sub = wid & 3, colh = wid >> 2;           // TMEM lane group / col half
    int row = sub * 32 + lid;

    // epilogue for a completed tile in TMEM buffer b
    auto epi = [&](int b, int erow0, int ecol0) {
        MBARRIER_WAIT_PARITY(sb + OFF_MB + b * 8, phs[b]);
        phs[b] ^= 1;
        TCGEN05_FENCE_AFTER();
        int gi = erow0 + row;
        int labR = g_lab[gi];
        const int* labB = (const int*)(smc + OFF_LAB + b * 512);
        float S = 0.f, P = 0.f;
        uint32_t d[32];
        #pragma unroll
        for (int half = 0; half < 2; half++) {
            TCGEN05_LD_X32(d, tbase + b * 128 + colh * 64 + half * 32);
            TCGEN05_WAIT_LD();
            int cbase = colh * 64 + half * 32;
            int jbase = ecol0 + cbase;
            #pragma unroll
            for (int c = 0; c < 32; c++) {
                float v = __uint_as_float(d[c]);
                float e;
                asm("ex2.approx.ftz.f32 %0, %1;" : "=f"(e) : "f"(v * EX2C));
                if ((jbase + c) != gi) {
                    S += e;
                    if (labB[cbase + c] == labR) P += v;
                }
            }
        }
        TCGEN05_FENCE_BEFORE();
        atomicAdd(&g_S[gi], S);
        atomicAdd(&g_P[gi], P);
    };

    for (int t = t0; t < t1; t++) {
        int rt = t >> 6, ct = t & 63;
        int p = t & 1;
        __syncthreads();   // all warps past previous iteration's epilogue/waits

        if (rt != curA) {  // band change: drain pending, then reload A
            if (pend >= 0) { epi(pend & 1, prow, pcol); pend = -1; }
            __syncthreads();
            const uint4* sH = g_hi + rt * 2048;
            const uint4* sL = g_lo + rt * 2048;
            uint4* dH = (uint4*)(smc + OFF_AHI);
            uint4* dL = (uint4*)(smc + OFF_ALO);
            for (int i = tid; i < 2048; i += 256) { dH[i] = sH[i]; dL[i] = sL[i]; }
            curA = rt;
        }
        {   // load B tile into buffer p (last MMA reader of buf p drained at t-1)
            const uint4* sH = g_hi + ct * 2048;
            const uint4* sL = g_lo + ct * 2048;
            uint4* dH = (uint4*)(smc + (p ? OFF_B1H : OFF_B0H));
            uint4* dL = (uint4*)(smc + (p ? OFF_B1L : OFF_B0L));
            for (int i = tid; i < 2048; i += 256) { dH[i] = sH[i]; dL[i] = sL[i]; }
            if (tid < 128) ((int*)(smc + OFF_LAB + p * 512))[tid] = g_lab[ct * TILE + tid];
        }
        __syncthreads();

        if (wid == 0) {
            TCGEN05_FENCE_AFTER();
            if (elect_one()) {
                uint32_t dtm = tbase + p * 128;
                uint64_t aH = MAKE_DESC(sb + OFF_AHI);
                uint64_t aL = MAKE_DESC(sb + OFF_ALO);
                uint64_t bH = MAKE_DESC(sb + (p ? OFF_B1H : OFF_B0H));
                uint64_t bL = MAKE_DESC(sb + (p ? OFF_B1L : OFF_B0L));
                #pragma unroll
                for (int ks = 0; ks < 8; ks++) mma_ss(dtm, aH + KOFF[ks], bH + KOFF[ks], ks > 0);
                #pragma unroll
                for (int ks = 0; ks < 8; ks++) mma_ss(dtm, aH + KOFF[ks], bL + KOFF[ks], 1u);
                #pragma unroll
                for (int ks = 0; ks < 8; ks++) mma_ss(dtm, aL + KOFF[ks], bH + KOFF[ks], 1u);
                TCGEN05_COMMIT(sb + OFF_MB + p * 8);
            }
        }

        // overlap: epilogue of tile t-1 (other TMEM buffer) runs under MMA t
        if (pend >= 0) epi(pend & 1, prow, pcol);
        pend = t; prow = rt * TILE; pcol = ct * TILE;
    }
    if (pend >= 0) epi(pend & 1, prow, pcol);

    __syncthreads();
    if (tid == 0) { MBARRIER_INVAL(sb + OFF_MB); MBARRIER_INVAL(sb + OFF_MB + 8); }
    __syncthreads();
    if (wid == 0) TCGEN05_DEALLOC(tbase, 512);
#endif  // TC_OK
}

// ---- fp32 SIMT fallback (proven); early-exits when tcgen05 live ----
__global__ __launch_bounds__(256, 3) void k_main_f32() {
    if (g_tc) return;
    extern __shared__ float sm[];
    float* As = sm;
    float* Bs = sm + 128 * BM;
    int*  labB = (int*)(sm + 2 * 128 * BM);

    int tid = threadIdx.x;
    int tx = tid & 15, ty = tid >> 4;

    int t0 = (int)(((long long)blockIdx.x       * TOT_TILES_F) / NBLK_F);
    int t1 = (int)(((long long)(blockIdx.x + 1) * TOT_TILES_F) / NBLK_F);

    int curRow = -1;
    float Sl[4] = {0.f, 0.f, 0.f, 0.f};
    float Pl[4] = {0.f, 0.f, 0.f, 0.f};
    int labR[4];

    for (int t = t0; t < t1; t++) {
        int rt = t / NTC_F, ct = t % NTC_F;
        int row0 = rt * BM, col0 = ct * BN;
        __syncthreads();
        if (rt != curRow) {
            if (curRow >= 0) {
                #pragma unroll
                for (int m = 0; m < 4; m++) {
                    float s = Sl[m], p = Pl[m];
                    #pragma unroll
                    for (int o = 8; o; o >>= 1) {
                        s += __shfl_xor_sync(0xffffffffu, s, o);
                        p += __shfl_xor_sync(0xffffffffu, p, o);
                    }
                    if (tx == 0) {
                        int r = curRow * BM + ty * 4 + m;
                        atomicAdd(&g_S[r], s);
                        atomicAdd(&g_P[r], p);
                    }
                    Sl[m] = 0.f; Pl[m] = 0.f;
                }
            }
            #pragma unroll
            for (int it = 0; it < 8; it++) {
                int i = it * 256 + tid;
                int k = i >> 4, q = i & 15;
                float4 v = ((const float4*)g_XT)[k * 2048 + (row0 >> 2) + q];
                *(float4*)&As[k * BM + q * 4] = v;
            }
            #pragma unroll
            for (int m = 0; m < 4; m++) labR[m] = g_lab[row0 + ty * 4 + m];
            curRow = rt;
        }
        #pragma unroll
        for (int it = 0; it < 8; it++) {
            int i = it * 256 + tid;
            int k = i >> 4, q = i & 15;
            float4 v = ((const float4*)g_XT)[k * 2048 + (col0 >> 2) + q];
            *(float4*)&Bs[k * BN + q * 4] = v;
        }
        if (tid < BN) labB[tid] = g_lab[col0 + tid];
        __syncthreads();

        float acc[4][4];
        #pragma unroll
        for (int m = 0; m < 4; m++)
            #pragma unroll
            for (int n = 0; n < 4; n++) acc[m][n] = 0.f;
        #pragma unroll 8
        for (int k = 0; k < 128; k++) {
            float4 a = *(const float4*)&As[k * BM + ty * 4];
            float4 b = *(const float4*)&Bs[k * BN + tx * 4];
            float av[4] = {a.x, a.y, a.z, a.w};
            float bv[4] = {b.x, b.y, b.z, b.w};
            #pragma unroll
            for (int m = 0; m < 4; m++)
                #pragma unroll
                for (int n = 0; n < 4; n++)
                    acc[m][n] = fmaf(av[m], bv[n], acc[m][n]);
        }
        int lj[4];
        #pragma unroll
        for (int n = 0; n < 4; n++) lj[n] = labB[tx * 4 + n];
        int gi0 = row0 + ty * 4, gj0 = col0 + tx * 4;
        #pragma unroll
        for (int m = 0; m < 4; m++) {
            int gi = gi0 + m;
            #pragma unroll
            for (int n = 0; n < 4; n++) {
                int gj = gj0 + n;
                float v = acc[m][n];
                if (gi != gj) {
                    Sl[m] += __expf(v * INV_T);
                    if (labR[m] == lj[n]) Pl[m] += v;
                }
            }
        }
    }
    if (curRow >= 0) {
        #pragma unroll
        for (int m = 0; m < 4; m++) {
            float s = Sl[m], p = Pl[m];
            #pragma unroll
            for (int o = 8; o; o >>= 1) {
                s += __shfl_xor_sync(0xffffffffu, s, o);
                p += __shfl_xor_sync(0xffffffffu, p, o);
            }
            if (tx == 0) {
                int r = curRow * BM + ty * 4 + m;
                atomicAdd(&g_S[r], s);
                atomicAdd(&g_P[r], p);
            }
        }
    }
}

__global__ void k_final(float* __restrict__ out) {
    __shared__ float shL[256], shW[256];
    int tid = threadIdx.x;
    float sl = 0.f, sw = 0.f;
    for (int i = tid; i < Nn; i += 256) {
        int L = g_lab[i];
        if (L != 0) {
            float cnt = (float)(g_hist[L] - 1);
            sl += logf(g_S[i]) - (g_P[i] * INV_T) / cnt;
            sw += 1.f;
        }
    }
    shL[tid] = sl; shW[tid] = sw;
    __syncthreads();
    for (int o = 128; o; o >>= 1) {
        if (tid < o) { shL[tid] += shL[tid + o]; shW[tid] += shW[tid + o]; }
        __syncthreads();
    }
    if (tid == 0) out[0] = shL[0] / shW[0];
}

extern "C" void kernel_launch(void* const* d_in, const int* in_sizes, int n_in,
                              void* d_out, int out_size) {
    (void)in_sizes; (void)n_in; (void)out_size;
    const float* feats  = (const float*)d_in[0];
    const int*   labels = (const int*)d_in[1];
    float*       out    = (float*)d_out;

    cudaFuncSetAttribute(k_main_tc, cudaFuncAttributeMaxDynamicSharedMemorySize, SMEM_SZ);
    cudaFuncSetAttribute(k_main_f32, cudaFuncAttributeMaxDynamicSharedMemorySize,
                         2 * 128 * BM * (int)sizeof(float) + BN * (int)sizeof(int));

    k_probe<<<1, 1>>>();
    k_zero<<<32, 256>>>();
    k_prep<<<2048, 256>>>(feats);
    k_repack<<<1024, 256>>>(feats);
    k_lab<<<32, 256>>>(labels);
    k_main_tc<<<NBLK_TC, 256, SMEM_SZ>>>();
    k_main_f32<<<NBLK_F, 256, 2 * 128 * BM * sizeof(float) + BN * sizeof(int)>>>();
    k_final<<<1, 256>>>(out);
}

// round 9
// speedup vs baseline: 1.2113x; 1.2113x over previous
#include <cuda_runtime.h>
#include <cuda_bf16.h>
#include <cstdint>

// SupConLoss: N=8192 embeddings (C=128, L2-normalized), logits = X X^T / T.
// tcgen05 bf16 hi/lo-split syrk + fused exp/mask epilogue. 3-stage pipeline:
// bulk-DMA B(t+1) || MMA(t) || epilogue(t-1). fp32 fallback retained.
// R8 fix: exactly ONE expect_tx per CPMB wait (R7 double-issued at band
// changes -> tx accumulation in one phase -> permanent wait -> timeout).

#define Nn 8192
#define TILE 128
#define NB 64
#define TOT_TILES (NB*NB)            // 4096 128x128 tiles
#define NBLK_TC 148
#define INV_T 14.285714285714285714f
#define EX2C 20.60992915555662f      // INV_T * log2(e)

#define BM 64
#define BN 64
#define NTC_F (Nn/BN)
#define TOT_TILES_F ((Nn/BM)*(Nn/BN))
#define NBLK_F 444

#if !defined(__CUDA_ARCH__)
#  define TC_OK 1
#elif defined(__CUDA_ARCH_FEAT_SM103_ALL) || defined(__CUDA_ARCH_FEAT_SM100_ALL) || \
      defined(__CUDA_ARCH_FEAT_SM101_ALL) || defined(__CUDA_ARCH_FAMILY_SPECIFIC__) || \
      defined(__CUDA_ARCH_SPECIFIC__)
#  define TC_OK 1
#else
#  define TC_OK 0
#endif

__device__ uint4 g_hi[Nn * 128 / 8];   // 2 MB blocked SW128-swizzled bf16 tiles
__device__ uint4 g_lo[Nn * 128 / 8];
__device__ float g_XT[128 * Nn];       // 4 MB k-major fp32 (fallback)
__device__ float g_S[Nn];
__device__ float g_P[Nn];
__device__ int   g_lab[Nn];
__device__ int   g_hist[4];
__device__ int   g_tc;

__device__ __forceinline__ uint32_t smem_u32(const void* p) {
    uint32_t a;
    asm("{ .reg .u64 t; cvta.to.shared.u64 t, %1; cvt.u32.u64 %0, t; }" : "=r"(a) : "l"(p));
    return a;
}
__device__ __forceinline__ uint32_t elect_one() {
    uint32_t pred;
    asm volatile("{ .reg .pred p; elect.sync _|p, 0xFFFFFFFF; selp.b32 %0, 1, 0, p; }" : "=r"(pred));
    return pred;
}
#define MBARRIER_INIT(mb, c) \
    asm volatile("mbarrier.init.shared.b64 [%0], %1;" :: "r"((uint32_t)(mb)), "r"((uint32_t)(c)) : "memory")
#define MBARRIER_INVAL(mb) \
    asm volatile("mbarrier.inval.shared.b64 [%0];" :: "r"((uint32_t)(mb)) : "memory")
#define MBARRIER_EXPECT_TX(mb, bytes) \
    asm volatile("mbarrier.arrive.expect_tx.shared.b64 _, [%0], %1;" \
                 :: "r"((uint32_t)(mb)), "r"((uint32_t)(bytes)) : "memory")
#define MBARRIER_WAIT_PARITY(mb, ph) do {                                          \
    uint32_t _m = (uint32_t)(mb), _p = (uint32_t)(ph), _d;                         \
    asm volatile("{ .reg .pred p; mbarrier.try_wait.parity.acquire.cta.shared::cta.b64 p, [%1], %2; selp.b32 %0, 1, 0, p; }" \
                 : "=r"(_d) : "r"(_m), "r"(_p) : "memory");                        \
    if (!_d) {                                                                     \
        asm volatile("{ .reg .pred P1; WL_%=: mbarrier.try_wait.parity.acquire.cta.shared::cta.b64 P1, [%0], %1, 0x989680; @P1 bra.uni WD_%=; bra.uni WL_%=; WD_%=: }" \
                     :: "r"(_m), "r"(_p) : "memory");                              \
    } } while (0)

#if TC_OK
#define TCGEN05_ALLOC(sa, n) \
    asm volatile("tcgen05.alloc.cta_group::1.sync.aligned.shared::cta.b32 [%0], %1;" \
                 :: "r"((uint32_t)(sa)), "r"((uint32_t)(n)) : "memory")
#define TCGEN05_DEALLOC(t, n) \
    asm volatile("tcgen05.dealloc.cta_group::1.sync.aligned.b32 %0, %1;" :: "r"(t), "r"((uint32_t)(n)))
#define TCGEN05_RELINQ() \
    asm volatile("tcgen05.relinquish_alloc_permit.cta_group::1.sync.aligned;")
#define TCGEN05_COMMIT(mb) \
    asm volatile("tcgen05.commit.cta_group::1.mbarrier::arrive::one.shared::cluster.b64 [%0];" \
                 :: "r"((uint32_t)(mb)) : "memory")
#define TCGEN05_WAIT_LD()      asm volatile("tcgen05.wait::ld.sync.aligned;" ::: "memory")
#define TCGEN05_FENCE_BEFORE() asm volatile("tcgen05.fence::before_thread_sync;" ::: "memory")
#define TCGEN05_FENCE_AFTER()  asm volatile("tcgen05.fence::after_thread_sync;" ::: "memory")
#define TCGEN05_LD_X32(r, a) \
    asm volatile("tcgen05.ld.sync.aligned.32x32b.x32.b32 " \
        "{%0,%1,%2,%3,%4,%5,%6,%7,%8,%9,%10,%11,%12,%13,%14,%15," \
        "%16,%17,%18,%19,%20,%21,%22,%23,%24,%25,%26,%27,%28,%29,%30,%31}, [%32];" \
        : "=r"((r)[0]),"=r"((r)[1]),"=r"((r)[2]),"=r"((r)[3]),"=r"((r)[4]),"=r"((r)[5]),"=r"((r)[6]),"=r"((r)[7]), \
          "=r"((r)[8]),"=r"((r)[9]),"=r"((r)[10]),"=r"((r)[11]),"=r"((r)[12]),"=r"((r)[13]),"=r"((r)[14]),"=r"((r)[15]), \
          "=r"((r)[16]),"=r"((r)[17]),"=r"((r)[18]),"=r"((r)[19]),"=r"((r)[20]),"=r"((r)[21]),"=r"((r)[22]),"=r"((r)[23]), \
          "=r"((r)[24]),"=r"((r)[25]),"=r"((r)[26]),"=r"((r)[27]),"=r"((r)[28]),"=r"((r)[29]),"=r"((r)[30]),"=r"((r)[31]) \
        : "r"(a))
// 1D bulk DMA global->shared with mbarrier completion (UBLKCP)
#define BULK_G2S(dst, src, size, mb) \
    asm volatile("cp.async.bulk.shared::cluster.global.mbarrier::complete_tx::bytes [%0], [%1], %2, [%3];" \
                 :: "r"((uint32_t)(dst)), "l"(src), "r"((uint32_t)(size)), "r"((uint32_t)(mb)) : "memory")

static constexpr uint64_t SMEM_DESC_BASE_SW128 =
    (uint64_t(2) << 61) | (uint64_t(1) << 46) | (uint64_t(64) << 32) | (uint64_t(1) << 16);
#define MAKE_DESC(addr) (SMEM_DESC_BASE_SW128 | ((uint64_t)((addr) >> 4) & 0x3FFF))

#define MMA_IDESC 0x08200490u   // F32 d, BF16 a/b, M=128, N=128
static __device__ __forceinline__ void mma_ss(uint32_t d, uint64_t a, uint64_t b, uint32_t en) {
    asm volatile("{ .reg .pred p; setp.ne.u32 p, %4, 0;\n\t"
        "tcgen05.mma.cta_group::1.kind::f16 [%0], %1, %2, %3, {%5,%5,%5,%5}, p; }"
        :: "r"(d), "l"(a), "l"(b), "r"(MMA_IDESC), "r"(en), "r"(0u) : "memory");
}
#endif  // TC_OK

// ---- smem layout (k_main_tc), bytes; tile bases 1024-aligned ----
#define OFF_AHI 0
#define OFF_ALO 32768
#define OFF_B0H 65536
#define OFF_B0L 98304
#define OFF_B1H 131072
#define OFF_B1L 163840
#define OFF_TP  196608
#define OFF_MB  196624    // 2 commit mbarriers
#define OFF_CPMB 196640   // 1 bulk-copy mbarrier
#define OFF_LAB 196648    // 3 x 512B label ring
#define SMEM_SZ 198192

__global__ void k_zero() {
    int i = blockIdx.x * 256 + threadIdx.x;
    if (i < Nn) { g_S[i] = 0.f; g_P[i] = 0.f; }
    if (i < 4) g_hist[i] = 0;
#if TC_OK
    if (i == 8) g_tc = 1;
#else
    if (i == 8) g_tc = 0;
#endif
}

// fp32 [B=4,V=2,C=128,HW=1024] -> bf16 hi/lo in blocked SW128 tile format.
__global__ void k_prep(const float* __restrict__ f) {
    int idx = blockIdx.x * 256 + threadIdx.x;   // 524288
    int n = idx & 8191;
    int j = idx >> 13;
    int vb = n >> 10, hw = n & 1023;
    int v = vb >> 2, b = vb & 3;
    const float* base = f + b * 262144 + v * 131072 + hw;
    float x0 = base[(2 * j) * 1024];
    float x1 = base[(2 * j + 1) * 1024];
    __nv_bfloat16 h0 = __float2bfloat16(x0);
    __nv_bfloat16 h1 = __float2bfloat16(x1);
    __nv_bfloat16 l0 = __float2bfloat16(x0 - __bfloat162float(h0));
    __nv_bfloat16 l1 = __float2bfloat16(x1 - __bfloat162float(h1));
    uint32_t hp = (uint32_t)__bfloat16_as_ushort(h0) | ((uint32_t)__bfloat16_as_ushort(h1) << 16);
    uint32_t lp = (uint32_t)__bfloat16_as_ushort(l0) | ((uint32_t)__bfloat16_as_ushort(l1) << 16);
    int band = n >> 7, r = n & 127, k = 2 * j;
    int atom = (r >> 3) + (k >> 6) * 16;
    uint32_t byte = atom * 1024 + (r & 7) * 128 + (k & 63) * 2;
    uint32_t sw = byte ^ ((byte >> 3) & 0x70);  // SW128
    uint32_t w = band * 8192 + (sw >> 2);
    ((uint32_t*)g_hi)[w] = hp;
    ((uint32_t*)g_lo)[w] = lp;
}

__global__ void k_lab(const int* __restrict__ labels) {
    int n = blockIdx.x * 256 + threadIdx.x;
    if (n >= Nn) return;
    int vb = n >> 10;
    int v = vb >> 2, b = vb & 3;
    int L = labels[b * 2048 + v * 1024 + (n & 1023)];
    g_lab[n] = L;
    atomicAdd(&g_hist[L], 1);
}

// fp32 k-major repack (fallback only)
__global__ void k_repack(const float* __restrict__ f) {
    if (g_tc) return;
    int base = blockIdx.x * 256 + threadIdx.x;
    #pragma unroll
    for (int r = 0; r < 4; r++) {
        int idx = r * 65536 + base;
        int q  = idx & 255;
        int t  = idx >> 8;
        int vb = t & 7;
        int c  = t >> 3;
        int v  = vb >> 2, b = vb & 3;
        float4 val = ((const float4*)f)[b * 65536 + v * 32768 + c * 256 + q];
        ((float4*)g_XT)[c * 2048 + vb * 256 + q] = val;
    }
}

// ---- tcgen05 main: 148 persistent CTAs, 8 warps, 3-stage pipeline ----
__global__ __launch_bounds__(256, 1) __cluster_dims__(1, 1, 1) void k_main_tc() {
#if TC_OK
    extern __shared__ char smc[];
    uint32_t sb = smem_u32(smc);
    int tid = threadIdx.x, wid = tid >> 5, lid = tid & 31;

    if (wid == 0) TCGEN05_ALLOC(sb + OFF_TP, 512);
    else          TCGEN05_RELINQ();
    __syncthreads();
    uint32_t tbase;
    asm volatile("ld.shared.b32 %0, [%1];" : "=r"(tbase) : "r"(sb + OFF_TP));
    if (tid == 0) {
        MBARRIER_INIT(sb + OFF_MB, 1);
        MBARRIER_INIT(sb + OFF_MB + 8, 1);
        MBARRIER_INIT(sb + OFF_CPMB, 1);
    }
    __syncthreads();

    const uint32_t KOFF[8] = {0, 2, 4, 6, 1024, 1026, 1028, 1030};  // 16B units

    int t0 = (int)(((long long)blockIdx.x * TOT_TILES) / NBLK_TC);
    int t1 = (int)(((long long)(blockIdx.x + 1) * TOT_TILES) / NBLK_TC);
    int phs[2] = {0, 0};
    int cpph = 0;
    int curA = t0 >> 6, pend = -1, prow = 0, pcol = 0;

    int sub = wid & 3, colh = wid >> 2;
    int row = sub * 32 + lid;

    // prefetch next B tile + its labels. INVARIANT: called at most once per
    // loop iteration, always after warp 0's CPMB wait for the current tile.
    auto prefetch = [&](int nxt) {
        if (nxt >= t1 || nxt < 0) return;
        int nct = nxt & 63, nb = nxt & 1;
        if (tid == 0) {
            MBARRIER_EXPECT_TX(sb + OFF_CPMB, 65536);
            BULK_G2S(sb + (nb ? OFF_B1H : OFF_B0H), (const char*)g_hi + nct * 32768, 32768, sb + OFF_CPMB);
            BULK_G2S(sb + (nb ? OFF_B1L : OFF_B0L), (const char*)g_lo + nct * 32768, 32768, sb + OFF_CPMB);
        }
        if (tid < 128) ((int*)(smc + OFF_LAB))[(nxt % 3) * 128 + tid] = g_lab[nct * TILE + tid];
    };

    // epilogue for completed tile in TMEM buffer b; optional prefetch of nxt
    auto epi = [&](int b, int erow0, int ecol0, int slot, int nxt) {
        MBARRIER_WAIT_PARITY(sb + OFF_MB + b * 8, phs[b]);
        phs[b] ^= 1;
        TCGEN05_FENCE_AFTER();
        prefetch(nxt);                       // B(nxt) buf proven free now
        int gi = erow0 + row;
        int labR = g_lab[gi];
        const int* labB = (const int*)(smc + OFF_LAB) + slot * 128;
        uint32_t d0[32], d1[32];
        TCGEN05_LD_X32(d0, tbase + b * 128 + colh * 64);
        TCGEN05_LD_X32(d1, tbase + b * 128 + colh * 64 + 32);
        TCGEN05_WAIT_LD();
        float S = 0.f, P = 0.f;
        int cb0 = colh * 64, jb0 = ecol0 + cb0;
        #pragma unroll
        for (int c = 0; c < 32; c++) {
            float v = __uint_as_float(d0[c]);
            float e;
            asm("ex2.approx.ftz.f32 %0, %1;" : "=f"(e) : "f"(v * EX2C));
            if ((jb0 + c) != gi) { S += e; if (labB[cb0 + c] == labR) P += v; }
        }
        int cb1 = cb0 + 32, jb1 = jb0 + 32;
        #pragma unroll
        for (int c = 0; c < 32; c++) {
            float v = __uint_as_float(d1[c]);
            float e;
            asm("ex2.approx.ftz.f32 %0, %1;" : "=f"(e) : "f"(v * EX2C));
            if ((jb1 + c) != gi) { S += e; if (labB[cb1 + c] == labR) P += v; }
        }
        TCGEN05_FENCE_BEFORE();
        atomicAdd(&g_S[gi], S);
        atomicAdd(&g_P[gi], P);
    };

    // prologue: load A band, prefetch B(t0) + labels(t0) (the ONE initial expect)
    {
        const uint4* sH = g_hi + curA * 2048;
        const uint4* sL = g_lo + curA * 2048;
        uint4* dH = (uint4*)(smc + OFF_AHI);
        uint4* dL = (uint4*)(smc + OFF_ALO);
        for (int i = tid; i < 2048; i += 256) { dH[i] = sH[i]; dL[i] = sL[i]; }
        int ct0 = t0 & 63, b0 = t0 & 1;
        if (tid == 0) {
            MBARRIER_EXPECT_TX(sb + OFF_CPMB, 65536);
            BULK_G2S(sb + (b0 ? OFF_B1H : OFF_B0H), (const char*)g_hi + ct0 * 32768, 32768, sb + OFF_CPMB);
            BULK_G2S(sb + (b0 ? OFF_B1L : OFF_B0L), (const char*)g_lo + ct0 * 32768, 32768, sb + OFF_CPMB);
        }
        if (tid < 128) ((int*)(smc + OFF_LAB))[(t0 % 3) * 128 + tid] = g_lab[ct0 * TILE + tid];
        __syncthreads();
    }

    for (int t = t0; t < t1; t++) {
        int rt = t >> 6, ct = t & 63;
        int p = t & 1;
        __syncthreads();   // all warps past epi(t-2); D/label reuse safe

        if (rt != curA) {  // band change: drain pending epilogue WITHOUT
                           // prefetch (B(t)'s expect_tx is already pending;
                           // the else-branch below issues prefetch(t+1))
            if (pend >= 0) { epi(pend & 1, prow, pcol, pend % 3, -1); pend = -1; }
            __syncthreads();
            const uint4* sH = g_hi + rt * 2048;
            const uint4* sL = g_lo + rt * 2048;
            uint4* dH = (uint4*)(smc + OFF_AHI);
            uint4* dL = (uint4*)(smc + OFF_ALO);
            for (int i = tid; i < 2048; i += 256) { dH[i] = sH[i]; dL[i] = sL[i]; }
            curA = rt;
            __syncthreads();
        }

        if (wid == 0) {    // wait bulk-DMA of B(t), then issue MMA chain
            MBARRIER_WAIT_PARITY(sb + OFF_CPMB, cpph);
            cpph ^= 1;
            TCGEN05_FENCE_AFTER();
            if (elect_one()) {
                uint32_t dtm = tbase + p * 128;
                uint64_t aH = MAKE_DESC(sb + OFF_AHI);
                uint64_t aL = MAKE_DESC(sb + OFF_ALO);
                uint64_t bH = MAKE_DESC(sb + (p ? OFF_B1H : OFF_B0H));
                uint64_t bL = MAKE_DESC(sb + (p ? OFF_B1L : OFF_B0L));
                #pragma unroll
                for (int ks = 0; ks < 8; ks++) mma_ss(dtm, aH + KOFF[ks], bH + KOFF[ks], ks > 0);
                #pragma unroll
                for (int ks = 0; ks < 8; ks++) mma_ss(dtm, aH + KOFF[ks], bL + KOFF[ks], 1u);
                #pragma unroll
                for (int ks = 0; ks < 8; ks++) mma_ss(dtm, aL + KOFF[ks], bH + KOFF[ks], 1u);
                TCGEN05_COMMIT(sb + OFF_MB + p * 8);
            }
        }

        // exactly one prefetch(t+1) per iteration, from whichever path runs
        if (pend >= 0) epi(pend & 1, prow, pcol, pend % 3, t + 1);
        else           prefetch(t + 1);   // first tile of a band / of the range
        pend = t; prow = rt * TILE; pcol = ct * TILE;
    }
    if (pend >= 0) epi(pend & 1, prow, pcol, pend % 3, -1);

    __syncthreads();
    if (tid == 0) {
        MBARRIER_INVAL(sb + OFF_MB); MBARRIER_INVAL(sb + OFF_MB + 8);
        MBARRIER_INVAL(sb + OFF_CPMB);
    }
    __syncthreads();
    if (wid == 0) TCGEN05_DEALLOC(tbase, 512);
#endif  // TC_OK
}

// ---- fp32 SIMT fallback (proven); early-exits when tcgen05 live ----
__global__ __launch_bounds__(256, 3) void k_main_f32() {
    if (g_tc) return;
    extern __shared__ float sm[];
    float* As = sm;
    float* Bs = sm + 128 * BM;
    int*  labB = (int*)(sm + 2 * 128 * BM);

    int tid = threadIdx.x;
    int tx = tid & 15, ty = tid >> 4;

    int t0 = (int)(((long long)blockIdx.x       * TOT_TILES_F) / NBLK_F);
    int t1 = (int)(((long long)(blockIdx.x + 1) * TOT_TILES_F) / NBLK_F);

    int curRow = -1;
    float Sl[4] = {0.f, 0.f, 0.f, 0.f};
    float Pl[4] = {0.f, 0.f, 0.f, 0.f};
    int labR[4];

    for (int t = t0; t < t1; t++) {
        int rt = t / NTC_F, ct = t % NTC_F;
        int row0 = rt * BM, col0 = ct * BN;
        __syncthreads();
        if (rt != curRow) {
            if (curRow >= 0) {
                #pragma unroll
                for (int m = 0; m < 4; m++) {
                    float s = Sl[m], p = Pl[m];
                    #pragma unroll
                    for (int o = 8; o; o >>= 1) {
                        s += __shfl_xor_sync(0xffffffffu, s, o);
                        p += __shfl_xor_sync(0xffffffffu, p, o);
                    }
                    if (tx == 0) {
                        int r = curRow * BM + ty * 4 + m;
                        atomicAdd(&g_S[r], s);
                        atomicAdd(&g_P[r], p);
                    }
                    Sl[m] = 0.f; Pl[m] = 0.f;
                }
            }
            #pragma unroll
            for (int it = 0; it < 8; it++) {
                int i = it * 256 + tid;
                int k = i >> 4, q = i & 15;
                float4 v = ((const float4*)g_XT)[k * 2048 + (row0 >> 2) + q];
                *(float4*)&As[k * BM + q * 4] = v;
            }
            #pragma unroll
            for (int m = 0; m < 4; m++) labR[m] = g_lab[row0 + ty * 4 + m];
            curRow = rt;
        }
        #pragma unroll
        for (int it = 0; it < 8; it++) {
            int i = it * 256 + tid;
            int k = i >> 4, q = i & 15;
            float4 v = ((const float4*)g_XT)[k * 2048 + (col0 >> 2) + q];
            *(float4*)&Bs[k * BN + q * 4] = v;
        }
        if (tid < BN) labB[tid] = g_lab[col0 + tid];
        __syncthreads();

        float acc[4][4];
        #pragma unroll
        for (int m = 0; m < 4; m++)
            #pragma unroll
            for (int n = 0; n < 4; n++) acc[m][n] = 0.f;
        #pragma unroll 8
        for (int k = 0; k < 128; k++) {
            float4 a = *(const float4*)&As[k * BM + ty * 4];
            float4 b = *(const float4*)&Bs[k * BN + tx * 4];
            float av[4] = {a.x, a.y, a.z, a.w};
            float bv[4] = {b.x, b.y, b.z, b.w};
            #pragma unroll
            for (int m = 0; m < 4; m++)
                #pragma unroll
                for (int n = 0; n < 4; n++)
                    acc[m][n] = fmaf(av[m], bv[n], acc[m][n]);
        }
        int lj[4];
        #pragma unroll
        for (int n = 0; n < 4; n++) lj[n] = labB[tx * 4 + n];
        int gi0 = row0 + ty * 4, gj0 = col0 + tx * 4;
        #pragma unroll
        for (int m = 0; m < 4; m++) {
            int gi = gi0 + m;
            #pragma unroll
            for (int n = 0; n < 4; n++) {
                int gj = gj0 + n;
                float v = acc[m][n];
                if (gi != gj) {
                    Sl[m] += __expf(v * INV_T);
                    if (labR[m] == lj[n]) Pl[m] += v;
                }
            }
        }
    }
    if (curRow >= 0) {
        #pragma unroll
        for (int m = 0; m < 4; m++) {
            float s = Sl[m], p = Pl[m];
            #pragma unroll
            for (int o = 8; o; o >>= 1) {
                s += __shfl_xor_sync(0xffffffffu, s, o);
                p += __shfl_xor_sync(0xffffffffu, p, o);
            }
            if (tx == 0) {
                int r = curRow * BM + ty * 4 + m;
                atomicAdd(&g_S[r], s);
                atomicAdd(&g_P[r], p);
            }
        }
    }
}

__global__ void k_final(float* __restrict__ out) {
    __shared__ float shL[256], shW[256];
    int tid = threadIdx.x;
    float sl = 0.f, sw = 0.f;
    for (int i = tid; i < Nn; i += 256) {
        int L = g_lab[i];
        if (L != 0) {
            float cnt = (float)(g_hist[L] - 1);
            sl += logf(g_S[i]) - (g_P[i] * INV_T) / cnt;
            sw += 1.f;
        }
    }
    shL[tid] = sl; shW[tid] = sw;
    __syncthreads();
    for (int o = 128; o; o >>= 1) {
        if (tid < o) { shL[tid] += shL[tid + o]; shW[tid] += shW[tid + o]; }
        __syncthreads();
    }
    if (tid == 0) out[0] = shL[0] / shW[0];
}

extern "C" void kernel_launch(void* const* d_in, const int* in_sizes, int n_in,
                              void* d_out, int out_size) {
    (void)in_sizes; (void)n_in; (void)out_size;
    const float* feats  = (const float*)d_in[0];
    const int*   labels = (const int*)d_in[1];
    float*       out    = (float*)d_out;

    cudaFuncSetAttribute(k_main_tc, cudaFuncAttributeMaxDynamicSharedMemorySize, SMEM_SZ);
    cudaFuncSetAttribute(k_main_f32, cudaFuncAttributeMaxDynamicSharedMemorySize,
                         2 * 128 * BM * (int)sizeof(float) + BN * (int)sizeof(int));

    // k_main_tc is launch #4: ncu's capture slot
    k_zero<<<32, 256>>>();
    k_prep<<<2048, 256>>>(feats);
    k_lab<<<32, 256>>>(labels);
    k_main_tc<<<NBLK_TC, 256, SMEM_SZ>>>();
    k_repack<<<256, 256>>>(feats);
    k_main_f32<<<NBLK_F, 256, 2 * 128 * BM * sizeof(float) + BN * sizeof(int)>>>();
    k_final<<<1, 256>>>(out);
}

// round 10
// speedup vs baseline: 1.2939x; 1.0682x over previous
#include <cuda_runtime.h>
#include <cuda_bf16.h>
#include <cstdint>

// SupConLoss: N=8192 embeddings (C=128, L2-normalized), logits = X X^T / T.
// tcgen05 bf16 hi/lo-split syrk; epilogue = pure exp-row-sum (P computed
// exactly via per-class feature sums: P_i = x_i . C_{lab_i} - 1).
// Inputs pre-scaled by sqrt(INV_T*log2e) so MMA outputs the ex2 argument.

#define Nn 8192
#define TILE 128
#define NB 64
#define TOT_TILES (NB*NB)            // 4096 128x128 tiles
#define NBLK_TC 148
#define INV_T 14.285714285714285714f
#define EX2C 20.60992915555662f      // INV_T * log2(e)
#define PSCALE 4.5398161f            // sqrt(EX2C)

#if !defined(__CUDA_ARCH__)
#  define TC_OK 1
#elif defined(__CUDA_ARCH_FEAT_SM103_ALL) || defined(__CUDA_ARCH_FEAT_SM100_ALL) || \
      defined(__CUDA_ARCH_FEAT_SM101_ALL) || defined(__CUDA_ARCH_FAMILY_SPECIFIC__) || \
      defined(__CUDA_ARCH_SPECIFIC__)
#  define TC_OK 1
#else
#  define TC_OK 0
#endif

__device__ uint4 g_hi[Nn * 128 / 8];   // 2 MB blocked SW128-swizzled bf16 tiles
__device__ uint4 g_lo[Nn * 128 / 8];
__device__ float g_S[Nn];
__device__ float g_P[Nn];              // x_i . C_{lab_i} - 1 (raw dot sum)
__device__ float g_C[4 * 128];         // per-class feature sums
__device__ int   g_lab[Nn];
__device__ int   g_hist[4];

__device__ __forceinline__ uint32_t smem_u32(const void* p) {
    uint32_t a;
    asm("{ .reg .u64 t; cvta.to.shared.u64 t, %1; cvt.u32.u64 %0, t; }" : "=r"(a) : "l"(p));
    return a;
}
__device__ __forceinline__ uint32_t elect_one() {
    uint32_t pred;
    asm volatile("{ .reg .pred p; elect.sync _|p, 0xFFFFFFFF; selp.b32 %0, 1, 0, p; }" : "=r"(pred));
    return pred;
}
#define MBARRIER_INIT(mb, c) \
    asm volatile("mbarrier.init.shared.b64 [%0], %1;" :: "r"((uint32_t)(mb)), "r"((uint32_t)(c)) : "memory")
#define MBARRIER_INVAL(mb) \
    asm volatile("mbarrier.inval.shared.b64 [%0];" :: "r"((uint32_t)(mb)) : "memory")
#define MBARRIER_EXPECT_TX(mb, bytes) \
    asm volatile("mbarrier.arrive.expect_tx.shared.b64 _, [%0], %1;" \
                 :: "r"((uint32_t)(mb)), "r"((uint32_t)(bytes)) : "memory")
#define MBARRIER_WAIT_PARITY(mb, ph) do {                                          \
    uint32_t _m = (uint32_t)(mb), _p = (uint32_t)(ph), _d;                         \
    asm volatile("{ .reg .pred p; mbarrier.try_wait.parity.acquire.cta.shared::cta.b64 p, [%1], %2; selp.b32 %0, 1, 0, p; }" \
                 : "=r"(_d) : "r"(_m), "r"(_p) : "memory");                        \
    if (!_d) {                                                                     \
        asm volatile("{ .reg .pred P1; WL_%=: mbarrier.try_wait.parity.acquire.cta.shared::cta.b64 P1, [%0], %1, 0x989680; @P1 bra.uni WD_%=; bra.uni WL_%=; WD_%=: }" \
                     :: "r"(_m), "r"(_p) : "memory");                              \
    } } while (0)

#if TC_OK
#define TCGEN05_ALLOC(sa, n) \
    asm volatile("tcgen05.alloc.cta_group::1.sync.aligned.shared::cta.b32 [%0], %1;" \
                 :: "r"((uint32_t)(sa)), "r"((uint32_t)(n)) : "memory")
#define TCGEN05_DEALLOC(t, n) \
    asm volatile("tcgen05.dealloc.cta_group::1.sync.aligned.b32 %0, %1;" :: "r"(t), "r"((uint32_t)(n)))
#define TCGEN05_RELINQ() \
    asm volatile("tcgen05.relinquish_alloc_permit.cta_group::1.sync.aligned;")
#define TCGEN05_COMMIT(mb) \
    asm volatile("tcgen05.commit.cta_group::1.mbarrier::arrive::one.shared::cluster.b64 [%0];" \
                 :: "r"((uint32_t)(mb)) : "memory")
#define TCGEN05_WAIT_LD()      asm volatile("tcgen05.wait::ld.sync.aligned;" ::: "memory")
#define TCGEN05_FENCE_BEFORE() asm volatile("tcgen05.fence::before_thread_sync;" ::: "memory")
#define TCGEN05_FENCE_AFTER()  asm volatile("tcgen05.fence::after_thread_sync;" ::: "memory")
#define TCGEN05_LD_X32(r, a) \
    asm volatile("tcgen05.ld.sync.aligned.32x32b.x32.b32 " \
        "{%0,%1,%2,%3,%4,%5,%6,%7,%8,%9,%10,%11,%12,%13,%14,%15," \
        "%16,%17,%18,%19,%20,%21,%22,%23,%24,%25,%26,%27,%28,%29,%30,%31}, [%32];" \
        : "=r"((r)[0]),"=r"((r)[1]),"=r"((r)[2]),"=r"((r)[3]),"=r"((r)[4]),"=r"((r)[5]),"=r"((r)[6]),"=r"((r)[7]), \
          "=r"((r)[8]),"=r"((r)[9]),"=r"((r)[10]),"=r"((r)[11]),"=r"((r)[12]),"=r"((r)[13]),"=r"((r)[14]),"=r"((r)[15]), \
          "=r"((r)[16]),"=r"((r)[17]),"=r"((r)[18]),"=r"((r)[19]),"=r"((r)[20]),"=r"((r)[21]),"=r"((r)[22]),"=r"((r)[23]), \
          "=r"((r)[24]),"=r"((r)[25]),"=r"((r)[26]),"=r"((r)[27]),"=r"((r)[28]),"=r"((r)[29]),"=r"((r)[30]),"=r"((r)[31]) \
        : "r"(a))
#define BULK_G2S(dst, src, size, mb) \
    asm volatile("cp.async.bulk.shared::cluster.global.mbarrier::complete_tx::bytes [%0], [%1], %2, [%3];" \
                 :: "r"((uint32_t)(dst)), "l"(src), "r"((uint32_t)(size)), "r"((uint32_t)(mb)) : "memory")

static constexpr uint64_t SMEM_DESC_BASE_SW128 =
    (uint64_t(2) << 61) | (uint64_t(1) << 46) | (uint64_t(64) << 32) | (uint64_t(1) << 16);
#define MAKE_DESC(addr) (SMEM_DESC_BASE_SW128 | ((uint64_t)((addr) >> 4) & 0x3FFF))

#define MMA_IDESC 0x08200490u   // F32 d, BF16 a/b, M=128, N=128
static __device__ __forceinline__ void mma_ss(uint32_t d, uint64_t a, uint64_t b, uint32_t en) {
    asm volatile("{ .reg .pred p; setp.ne.u32 p, %4, 0;\n\t"
        "tcgen05.mma.cta_group::1.kind::f16 [%0], %1, %2, %3, {%5,%5,%5,%5}, p; }"
        :: "r"(d), "l"(a), "l"(b), "r"(MMA_IDESC), "r"(en), "r"(0u) : "memory");
}
#endif  // TC_OK

// ---- smem layout (k_main_tc), bytes; tile bases 1024-aligned ----
#define OFF_AHI 0
#define OFF_ALO 32768
#define OFF_B0H 65536
#define OFF_B0L 98304
#define OFF_B1H 131072
#define OFF_B1L 163840
#define OFF_TP  196608
#define OFF_MB  196624    // 2 commit mbarriers
#define OFF_CPMB 196640   // 1 bulk-copy mbarrier
#define SMEM_SZ 196656

__global__ void k_zero() {
    int i = blockIdx.x * 256 + threadIdx.x;
    if (i < Nn) g_S[i] = 0.f;
    if (i < 512) g_C[i] = 0.f;
    if (i < 4) g_hist[i] = 0;
}

// fp32 [B=4,V=2,C=128,HW=1024], PRE-SCALED by sqrt(EX2C) -> bf16 hi/lo in
// blocked SW128 tile format (16 atom-rows x 2 atom-cols per 128-row band).
__global__ void k_prep(const float* __restrict__ f) {
    int idx = blockIdx.x * 256 + threadIdx.x;   // 524288
    int n = idx & 8191;
    int j = idx >> 13;
    int vb = n >> 10, hw = n & 1023;
    int v = vb >> 2, b = vb & 3;
    const float* base = f + b * 262144 + v * 131072 + hw;
    float x0 = base[(2 * j) * 1024] * PSCALE;
    float x1 = base[(2 * j + 1) * 1024] * PSCALE;
    __nv_bfloat16 h0 = __float2bfloat16(x0);
    __nv_bfloat16 h1 = __float2bfloat16(x1);
    __nv_bfloat16 l0 = __float2bfloat16(x0 - __bfloat162float(h0));
    __nv_bfloat16 l1 = __float2bfloat16(x1 - __bfloat162float(h1));
    uint32_t hp = (uint32_t)__bfloat16_as_ushort(h0) | ((uint32_t)__bfloat16_as_ushort(h1) << 16);
    uint32_t lp = (uint32_t)__bfloat16_as_ushort(l0) | ((uint32_t)__bfloat16_as_ushort(l1) << 16);
    int band = n >> 7, r = n & 127, k = 2 * j;
    int atom = (r >> 3) + (k >> 6) * 16;
    uint32_t byte = atom * 1024 + (r & 7) * 128 + (k & 63) * 2;
    uint32_t sw = byte ^ ((byte >> 3) & 0x70);  // SW128
    uint32_t w = band * 8192 + (sw >> 2);
    ((uint32_t*)g_hi)[w] = hp;
    ((uint32_t*)g_lo)[w] = lp;
}

__global__ void k_lab(const int* __restrict__ labels) {
    int n = blockIdx.x * 256 + threadIdx.x;
    if (n >= Nn) return;
    int vb = n >> 10;
    int v = vb >> 2, b = vb & 3;
    int L = labels[b * 2048 + v * 1024 + (n & 1023)];
    g_lab[n] = L;
    atomicAdd(&g_hist[L], 1);
}

// per-class feature sums: C_L[c] = sum_{lab_n = L} x_n[c].
// grid 1024: block = (vb, c); 256 threads x 4 hw each (float4 coalesced).
__global__ void k_csum(const float* __restrict__ f) {
    int bid = blockIdx.x;
    int vb = bid >> 7, c = bid & 127;
    int v = vb >> 2, b = vb & 3;
    int tid = threadIdx.x;
    float4 x = ((const float4*)(f + b * 262144 + v * 131072 + c * 1024))[tid];
    int4  l = ((const int4*)(g_lab + vb * 1024))[tid];
    float s[4] = {0.f, 0.f, 0.f, 0.f};
    s[l.x] += x.x; s[l.y] += x.y; s[l.z] += x.z; s[l.w] += x.w;
    #pragma unroll
    for (int q = 0; q < 4; q++) {
        float r = s[q];
        #pragma unroll
        for (int o = 16; o; o >>= 1) r += __shfl_xor_sync(0xffffffffu, r, o);
        if ((tid & 31) == 0 && r != 0.f) atomicAdd(&g_C[q * 128 + c], r);
    }
}

// P_i = x_i . C_{lab_i} - 1  (exact positive-pair dot sum, diag removed)
// grid 32: block handles 256 consecutive n (one vb per block group).
__global__ void k_dotp(const float* __restrict__ f) {
    __shared__ float sC[512];
    int tid = threadIdx.x;
    int n = blockIdx.x * 256 + tid;
    int vb = n >> 10, hw = n & 1023;
    int v = vb >> 2, b = vb & 3;
    ((float2*)sC)[tid] = ((const float2*)g_C)[tid];
    __syncthreads();
    const float* base = f + b * 262144 + v * 131072 + hw;
    const float* C = sC + g_lab[n] * 128;
    float acc = 0.f;
    #pragma unroll 16
    for (int c = 0; c < 128; c++) acc = fmaf(base[c * 1024], C[c], acc);
    g_P[n] = acc - 1.f;
}

// ---- tcgen05 main: 148 persistent CTAs, 8 warps, 3-stage pipeline ----
__global__ __launch_bounds__(256, 1) __cluster_dims__(1, 1, 1) void k_main_tc() {
#if TC_OK
    extern __shared__ char smc[];
    uint32_t sb = smem_u32(smc);
    int tid = threadIdx.x, wid = tid >> 5, lid = tid & 31;

    if (wid == 0) TCGEN05_ALLOC(sb + OFF_TP, 512);
    else          TCGEN05_RELINQ();
    __syncthreads();
    uint32_t tbase;
    asm volatile("ld.shared.b32 %0, [%1];" : "=r"(tbase) : "r"(sb + OFF_TP));
    if (tid == 0) {
        MBARRIER_INIT(sb + OFF_MB, 1);
        MBARRIER_INIT(sb + OFF_MB + 8, 1);
        MBARRIER_INIT(sb + OFF_CPMB, 1);
    }
    __syncthreads();

    const uint32_t KOFF[8] = {0, 2, 4, 6, 1024, 1026, 1028, 1030};  // 16B units

    int t0 = (int)(((long long)blockIdx.x * TOT_TILES) / NBLK_TC);
    int t1 = (int)(((long long)(blockIdx.x + 1) * TOT_TILES) / NBLK_TC);
    int phs[2] = {0, 0};
    int cpph = 0;
    int curA = t0 >> 6, pend = -1, prow = 0, pcol = 0;

    int sub = wid & 3, colh = wid >> 2;
    int row = sub * 32 + lid;

    // one expect_tx per CPMB wait, strictly alternating (R8 invariant)
    auto prefetch = [&](int nxt) {
        if (nxt >= t1 || nxt < 0) return;
        if (tid == 0) {
            int nct = nxt & 63, nb = nxt & 1;
            MBARRIER_EXPECT_TX(sb + OFF_CPMB, 65536);
            BULK_G2S(sb + (nb ? OFF_B1H : OFF_B0H), (const char*)g_hi + nct * 32768, 32768, sb + OFF_CPMB);
            BULK_G2S(sb + (nb ? OFF_B1L : OFF_B0L), (const char*)g_lo + nct * 32768, 32768, sb + OFF_CPMB);
        }
    };

    // epilogue: pure exp row-sum of completed tile in TMEM buffer b
    auto epi = [&](int b, int erow0, int ecol0, int nxt) {
        MBARRIER_WAIT_PARITY(sb + OFF_MB + b * 8, phs[b]);
        phs[b] ^= 1;
        TCGEN05_FENCE_AFTER();
        prefetch(nxt);                       // B(nxt) buf proven free now
        int gi = erow0 + row;
        uint32_t d0[32], d1[32];
        TCGEN05_LD_X32(d0, tbase + b * 128 + colh * 64);
        TCGEN05_LD_X32(d1, tbase + b * 128 + colh * 64 + 32);
        TCGEN05_WAIT_LD();
        float S = 0.f;
        if (erow0 == ecol0) {                // diagonal tile: exclude j == i
            int jb0 = ecol0 + colh * 64;
            #pragma unroll
            for (int c = 0; c < 32; c++) {
                float e;
                asm("ex2.approx.ftz.f32 %0, %1;" : "=f"(e) : "f"(__uint_as_float(d0[c])));
                if ((jb0 + c) != gi) S += e;
            }
            #pragma unroll
            for (int c = 0; c < 32; c++) {
                float e;
                asm("ex2.approx.ftz.f32 %0, %1;" : "=f"(e) : "f"(__uint_as_float(d1[c])));
                if ((jb0 + 32 + c) != gi) S += e;
            }
        } else {
            #pragma unroll
            for (int c = 0; c < 32; c++) {
                float e0, e1;
                asm("ex2.approx.ftz.f32 %0, %1;" : "=f"(e0) : "f"(__uint_as_float(d0[c])));
                asm("ex2.approx.ftz.f32 %0, %1;" : "=f"(e1) : "f"(__uint_as_float(d1[c])));
                S += e0; S += e1;
            }
        }
        TCGEN05_FENCE_BEFORE();
        atomicAdd(&g_S[gi], S);
    };

    // prologue: load A band, prefetch B(t0) (the ONE initial expect)
    {
        const uint4* sH = g_hi + curA * 2048;
        const uint4* sL = g_lo + curA * 2048;
        uint4* dH = (uint4*)(smc + OFF_AHI);
        uint4* dL = (uint4*)(smc + OFF_ALO);
        for (int i = tid; i < 2048; i += 256) { dH[i] = sH[i]; dL[i] = sL[i]; }
        if (tid == 0) {
            int ct0 = t0 & 63, b0 = t0 & 1;
            MBARRIER_EXPECT_TX(sb + OFF_CPMB, 65536);
            BULK_G2S(sb + (b0 ? OFF_B1H : OFF_B0H), (const char*)g_hi + ct0 * 32768, 32768, sb + OFF_CPMB);
            BULK_G2S(sb + (b0 ? OFF_B1L : OFF_B0L), (const char*)g_lo + ct0 * 32768, 32768, sb + OFF_CPMB);
        }
        __syncthreads();
    }

    for (int t = t0; t < t1; t++) {
        int rt = t >> 6, ct = t & 63;
        int p = t & 1;
        __syncthreads();   // all warps past epi(t-2); D reuse safe

        if (rt != curA) {  // band change: drain (no prefetch: B(t) expect is
                           // already pending; else-branch below issues t+1)
            if (pend >= 0) { epi(pend & 1, prow, pcol, -1); pend = -1; }
            __syncthreads();
            const uint4* sH = g_hi + rt * 2048;
            const uint4* sL = g_lo + rt * 2048;
            uint4* dH = (uint4*)(smc + OFF_AHI);
            uint4* dL = (uint4*)(smc + OFF_ALO);
            for (int i = tid; i < 2048; i += 256) { dH[i] = sH[i]; dL[i] = sL[i]; }
            curA = rt;
            __syncthreads();
        }

        if (wid == 0) {    // wait bulk-DMA of B(t), then issue MMA chain
            MBARRIER_WAIT_PARITY(sb + OFF_CPMB, cpph);
            cpph ^= 1;
            TCGEN05_FENCE_AFTER();
            if (elect_one()) {
                uint32_t dtm = tbase + p * 128;
                uint64_t aH = MAKE_DESC(sb + OFF_AHI);
                uint64_t aL = MAKE_DESC(sb + OFF_ALO);
                uint64_t bH = MAKE_DESC(sb + (p ? OFF_B1H : OFF_B0H));
                uint64_t bL = MAKE_DESC(sb + (p ? OFF_B1L : OFF_B0L));
                #pragma unroll
                for (int ks = 0; ks < 8; ks++) mma_ss(dtm, aH + KOFF[ks], bH + KOFF[ks], ks > 0);
                #pragma unroll
                for (int ks = 0; ks < 8; ks++) mma_ss(dtm, aH + KOFF[ks], bL + KOFF[ks], 1u);
                #pragma unroll
                for (int ks = 0; ks < 8; ks++) mma_ss(dtm, aL + KOFF[ks], bH + KOFF[ks], 1u);
                TCGEN05_COMMIT(sb + OFF_MB + p * 8);
            }
        }

        // exactly one prefetch(t+1) per iteration
        if (pend >= 0) epi(pend & 1, prow, pcol, t + 1);
        else           prefetch(t + 1);
        pend = t; prow = rt * TILE; pcol = ct * TILE;
    }
    if (pend >= 0) epi(pend & 1, prow, pcol, -1);

    __syncthreads();
    if (tid == 0) {
        MBARRIER_INVAL(sb + OFF_MB); MBARRIER_INVAL(sb + OFF_MB + 8);
        MBARRIER_INVAL(sb + OFF_CPMB);
    }
    __syncthreads();
    if (wid == 0) TCGEN05_DEALLOC(tbase, 512);
#endif  // TC_OK
}

__global__ void k_final(float* __restrict__ out) {
    __shared__ float shL[256], shW[256];
    int tid = threadIdx.x;
    float sl = 0.f, sw = 0.f;
    for (int i = tid; i < Nn; i += 256) {
        int L = g_lab[i];
        if (L != 0) {
            float cnt = (float)(g_hist[L] - 1);
            sl += logf(g_S[i]) - (g_P[i] * INV_T) / cnt;
            sw += 1.f;
        }
    }
    shL[tid] = sl; shW[tid] = sw;
    __syncthreads();
    for (int o = 128; o; o >>= 1) {
        if (tid < o) { shL[tid] += shL[tid + o]; shW[tid] += shW[tid + o]; }
        __syncthreads();
    }
    if (tid == 0) out[0] = shL[0] / shW[0];
}

extern "C" void kernel_launch(void* const* d_in, const int* in_sizes, int n_in,
                              void* d_out, int out_size) {
    (void)in_sizes; (void)n_in; (void)out_size;
    const float* feats  = (const float*)d_in[0];
    const int*   labels = (const int*)d_in[1];
    float*       out    = (float*)d_out;

    cudaFuncSetAttribute(k_main_tc, cudaFuncAttributeMaxDynamicSharedMemorySize, SMEM_SZ);

    // k_main_tc is launch #4 (ncu capture slot)
    k_zero<<<32, 256>>>();
    k_prep<<<2048, 256>>>(feats);
    k_lab<<<32, 256>>>(labels);
    k_main_tc<<<NBLK_TC, 256, SMEM_SZ>>>();
    k_csum<<<1024, 256>>>(feats);
    k_dotp<<<32, 256>>>(feats);
    k_final<<<1, 256>>>(out);
}

// round 11
// speedup vs baseline: 1.4536x; 1.1234x over previous
#include <cuda_runtime.h>
#include <cuda_bf16.h>
#include <cstdint>

// SupConLoss: N=8192 embeddings (C=128, L2-normalized), logits = X X^T / T.
// tcgen05 bf16 hi/lo-split syrk over the UPPER TRIANGLE only (2080 tiles);
// each off-diag tile yields row sums AND column sums (symmetry). P computed
// exactly via per-class sums. Inputs pre-scaled by sqrt(INV_T*log2e).

#define Nn 8192
#define TILE 128
#define NB 64
#define TRI_TILES 2080               // 64*65/2
#define NBLK_TC 148
#define INV_T 14.285714285714285714f
#define EX2C 20.60992915555662f      // INV_T * log2(e)
#define PSCALE 4.5398161f            // sqrt(EX2C)

#if !defined(__CUDA_ARCH__)
#  define TC_OK 1
#elif defined(__CUDA_ARCH_FEAT_SM103_ALL) || defined(__CUDA_ARCH_FEAT_SM100_ALL) || \
      defined(__CUDA_ARCH_FEAT_SM101_ALL) || defined(__CUDA_ARCH_FAMILY_SPECIFIC__) || \
      defined(__CUDA_ARCH_SPECIFIC__)
#  define TC_OK 1
#else
#  define TC_OK 0
#endif

__device__ uint4 g_hi[Nn * 128 / 8];   // 2 MB blocked SW128-swizzled bf16 tiles
__device__ uint4 g_lo[Nn * 128 / 8];
__device__ float g_S[Nn];
__device__ float g_P[Nn];              // x_i . C_{lab_i} - 1
__device__ float g_C[4 * 128];         // per-class feature sums
__device__ int   g_lab[Nn];
__device__ int   g_hist[4];

__device__ __forceinline__ uint32_t smem_u32(const void* p) {
    uint32_t a;
    asm("{ .reg .u64 t; cvta.to.shared.u64 t, %1; cvt.u32.u64 %0, t; }" : "=r"(a) : "l"(p));
    return a;
}
__device__ __forceinline__ uint32_t elect_one() {
    uint32_t pred;
    asm volatile("{ .reg .pred p; elect.sync _|p, 0xFFFFFFFF; selp.b32 %0, 1, 0, p; }" : "=r"(pred));
    return pred;
}
#define MBARRIER_INIT(mb, c) \
    asm volatile("mbarrier.init.shared.b64 [%0], %1;" :: "r"((uint32_t)(mb)), "r"((uint32_t)(c)) : "memory")
#define MBARRIER_INVAL(mb) \
    asm volatile("mbarrier.inval.shared.b64 [%0];" :: "r"((uint32_t)(mb)) : "memory")
#define MBARRIER_EXPECT_TX(mb, bytes) \
    asm volatile("mbarrier.arrive.expect_tx.shared.b64 _, [%0], %1;" \
                 :: "r"((uint32_t)(mb)), "r"((uint32_t)(bytes)) : "memory")
#define MBARRIER_WAIT_PARITY(mb, ph) do {                                          \
    uint32_t _m = (uint32_t)(mb), _p = (uint32_t)(ph), _d;                         \
    asm volatile("{ .reg .pred p; mbarrier.try_wait.parity.acquire.cta.shared::cta.b64 p, [%1], %2; selp.b32 %0, 1, 0, p; }" \
                 : "=r"(_d) : "r"(_m), "r"(_p) : "memory");                        \
    if (!_d) {                                                                     \
        asm volatile("{ .reg .pred P1; WL_%=: mbarrier.try_wait.parity.acquire.cta.shared::cta.b64 P1, [%0], %1, 0x989680; @P1 bra.uni WD_%=; bra.uni WL_%=; WD_%=: }" \
                     :: "r"(_m), "r"(_p) : "memory");                              \
    } } while (0)

#if TC_OK
#define TCGEN05_ALLOC(sa, n) \
    asm volatile("tcgen05.alloc.cta_group::1.sync.aligned.shared::cta.b32 [%0], %1;" \
                 :: "r"((uint32_t)(sa)), "r"((uint32_t)(n)) : "memory")
#define TCGEN05_DEALLOC(t, n) \
    asm volatile("tcgen05.dealloc.cta_group::1.sync.aligned.b32 %0, %1;" :: "r"(t), "r"((uint32_t)(n)))
#define TCGEN05_RELINQ() \
    asm volatile("tcgen05.relinquish_alloc_permit.cta_group::1.sync.aligned;")
#define TCGEN05_COMMIT(mb) \
    asm volatile("tcgen05.commit.cta_group::1.mbarrier::arrive::one.shared::cluster.b64 [%0];" \
                 :: "r"((uint32_t)(mb)) : "memory")
#define TCGEN05_WAIT_LD()      asm volatile("tcgen05.wait::ld.sync.aligned;" ::: "memory")
#define TCGEN05_FENCE_BEFORE() asm volatile("tcgen05.fence::before_thread_sync;" ::: "memory")
#define TCGEN05_FENCE_AFTER()  asm volatile("tcgen05.fence::after_thread_sync;" ::: "memory")
#define TCGEN05_LD_X32(r, a) \
    asm volatile("tcgen05.ld.sync.aligned.32x32b.x32.b32 " \
        "{%0,%1,%2,%3,%4,%5,%6,%7,%8,%9,%10,%11,%12,%13,%14,%15," \
        "%16,%17,%18,%19,%20,%21,%22,%23,%24,%25,%26,%27,%28,%29,%30,%31}, [%32];" \
        : "=r"((r)[0]),"=r"((r)[1]),"=r"((r)[2]),"=r"((r)[3]),"=r"((r)[4]),"=r"((r)[5]),"=r"((r)[6]),"=r"((r)[7]), \
          "=r"((r)[8]),"=r"((r)[9]),"=r"((r)[10]),"=r"((r)[11]),"=r"((r)[12]),"=r"((r)[13]),"=r"((r)[14]),"=r"((r)[15]), \
          "=r"((r)[16]),"=r"((r)[17]),"=r"((r)[18]),"=r"((r)[19]),"=r"((r)[20]),"=r"((r)[21]),"=r"((r)[22]),"=r"((r)[23]), \
          "=r"((r)[24]),"=r"((r)[25]),"=r"((r)[26]),"=r"((r)[27]),"=r"((r)[28]),"=r"((r)[29]),"=r"((r)[30]),"=r"((r)[31]) \
        : "r"(a))
#define BULK_G2S(dst, src, size, mb) \
    asm volatile("cp.async.bulk.shared::cluster.global.mbarrier::complete_tx::bytes [%0], [%1], %2, [%3];" \
                 :: "r"((uint32_t)(dst)), "l"(src), "r"((uint32_t)(size)), "r"((uint32_t)(mb)) : "memory")

static constexpr uint64_t SMEM_DESC_BASE_SW128 =
    (uint64_t(2) << 61) | (uint64_t(1) << 46) | (uint64_t(64) << 32) | (uint64_t(1) << 16);
#define MAKE_DESC(addr) (SMEM_DESC_BASE_SW128 | ((uint64_t)((addr) >> 4) & 0x3FFF))

#define MMA_IDESC 0x08200490u   // F32 d, BF16 a/b, M=128, N=128
static __device__ __forceinline__ void mma_ss(uint32_t d, uint64_t a, uint64_t b, uint32_t en) {
    asm volatile("{ .reg .pred p; setp.ne.u32 p, %4, 0;\n\t"
        "tcgen05.mma.cta_group::1.kind::f16 [%0], %1, %2, %3, {%5,%5,%5,%5}, p; }"
        :: "r"(d), "l"(a), "l"(b), "r"(MMA_IDESC), "r"(en), "r"(0u) : "memory");
}
#endif  // TC_OK

// ---- smem layout (k_main_tc), bytes; tile bases 1024-aligned ----
#define OFF_AHI 0
#define OFF_ALO 32768
#define OFF_B0H 65536
#define OFF_B0L 98304
#define OFF_B1H 131072
#define OFF_B1L 163840
#define OFF_TP   196608
#define OFF_MB   196624   // 2 commit mbarriers
#define OFF_CPMB 196640   // 1 bulk-copy mbarrier
#define OFF_SCOL 196656   // 4 x 128 floats (col-sum combine)
#define SMEM_SZ  198704

__global__ void k_zero() {
    int i = blockIdx.x * 256 + threadIdx.x;
    if (i < Nn) g_S[i] = 0.f;
    if (i < 512) g_C[i] = 0.f;
    if (i < 4) g_hist[i] = 0;
}

// fp32 [B=4,V=2,C=128,HW=1024], PRE-SCALED by sqrt(EX2C) -> bf16 hi/lo in
// blocked SW128 tile format.
__global__ void k_prep(const float* __restrict__ f) {
    int idx = blockIdx.x * 256 + threadIdx.x;   // 524288
    int n = idx & 8191;
    int j = idx >> 13;
    int vb = n >> 10, hw = n & 1023;
    int v = vb >> 2, b = vb & 3;
    const float* base = f + b * 262144 + v * 131072 + hw;
    float x0 = base[(2 * j) * 1024] * PSCALE;
    float x1 = base[(2 * j + 1) * 1024] * PSCALE;
    __nv_bfloat16 h0 = __float2bfloat16(x0);
    __nv_bfloat16 h1 = __float2bfloat16(x1);
    __nv_bfloat16 l0 = __float2bfloat16(x0 - __bfloat162float(h0));
    __nv_bfloat16 l1 = __float2bfloat16(x1 - __bfloat162float(h1));
    uint32_t hp = (uint32_t)__bfloat16_as_ushort(h0) | ((uint32_t)__bfloat16_as_ushort(h1) << 16);
    uint32_t lp = (uint32_t)__bfloat16_as_ushort(l0) | ((uint32_t)__bfloat16_as_ushort(l1) << 16);
    int band = n >> 7, r = n & 127, k = 2 * j;
    int atom = (r >> 3) + (k >> 6) * 16;
    uint32_t byte = atom * 1024 + (r & 7) * 128 + (k & 63) * 2;
    uint32_t sw = byte ^ ((byte >> 3) & 0x70);  // SW128
    uint32_t w = band * 8192 + (sw >> 2);
    ((uint32_t*)g_hi)[w] = hp;
    ((uint32_t*)g_lo)[w] = lp;
}

__global__ void k_lab(const int* __restrict__ labels) {
    int n = blockIdx.x * 256 + threadIdx.x;
    if (n >= Nn) return;
    int vb = n >> 10;
    int v = vb >> 2, b = vb & 3;
    int L = labels[b * 2048 + v * 1024 + (n & 1023)];
    g_lab[n] = L;
    atomicAdd(&g_hist[L], 1);
}

// per-class feature sums
__global__ void k_csum(const float* __restrict__ f) {
    int bid = blockIdx.x;
    int vb = bid >> 7, c = bid & 127;
    int v = vb >> 2, b = vb & 3;
    int tid = threadIdx.x;
    float4 x = ((const float4*)(f + b * 262144 + v * 131072 + c * 1024))[tid];
    int4  l = ((const int4*)(g_lab + vb * 1024))[tid];
    float s[4] = {0.f, 0.f, 0.f, 0.f};
    s[l.x] += x.x; s[l.y] += x.y; s[l.z] += x.z; s[l.w] += x.w;
    #pragma unroll
    for (int q = 0; q < 4; q++) {
        float r = s[q];
        #pragma unroll
        for (int o = 16; o; o >>= 1) r += __shfl_xor_sync(0xffffffffu, r, o);
        if ((tid & 31) == 0 && r != 0.f) atomicAdd(&g_C[q * 128 + c], r);
    }
}

// P_i = x_i . C_{lab_i} - 1
__global__ void k_dotp(const float* __restrict__ f) {
    __shared__ float sC[512];
    int tid = threadIdx.x;
    int n = blockIdx.x * 256 + tid;
    int vb = n >> 10, hw = n & 1023;
    int v = vb >> 2, b = vb & 3;
    ((float2*)sC)[tid] = ((const float2*)g_C)[tid];
    __syncthreads();
    const float* base = f + b * 262144 + v * 131072 + hw;
    const float* C = sC + g_lab[n] * 128;
    float acc = 0.f;
    #pragma unroll 16
    for (int c = 0; c < 128; c++) acc = fmaf(base[c * 1024], C[c], acc);
    g_P[n] = acc - 1.f;
}

// ---- tcgen05 main: upper-triangle tiles, 148 persistent CTAs, 8 warps ----
__global__ __launch_bounds__(256, 1) __cluster_dims__(1, 1, 1) void k_main_tc() {
#if TC_OK
    extern __shared__ char smc[];
    uint32_t sb = smem_u32(smc);
    int tid = threadIdx.x, wid = tid >> 5, lid = tid & 31;

    if (wid == 0) TCGEN05_ALLOC(sb + OFF_TP, 512);
    else          TCGEN05_RELINQ();
    __syncthreads();
    uint32_t tbase;
    asm volatile("ld.shared.b32 %0, [%1];" : "=r"(tbase) : "r"(sb + OFF_TP));
    if (tid == 0) {
        MBARRIER_INIT(sb + OFF_MB, 1);
        MBARRIER_INIT(sb + OFF_MB + 8, 1);
        MBARRIER_INIT(sb + OFF_CPMB, 1);
    }
    __syncthreads();

    const uint32_t KOFF[8] = {0, 2, 4, 6, 1024, 1026, 1028, 1030};  // 16B units

    int s0 = (int)(((long long)blockIdx.x * TRI_TILES) / NBLK_TC);
    int s1 = (int)(((long long)(blockIdx.x + 1) * TRI_TILES) / NBLK_TC);
    // map s0 -> (rt, ct): cum(r) = r*64 - r*(r-1)/2 tiles before band r
    int rt = 0;
    while ((rt + 1) * 64 - ((rt + 1) * rt) / 2 <= s0) rt++;
    int ct = rt + (s0 - (rt * 64 - (rt * (rt - 1)) / 2));

    int phs[2] = {0, 0};
    int cpph = 0;
    int curA = rt, pend = -1, prow = 0, pcol = 0;

    int sub = wid & 3, colh = wid >> 2;
    int row = sub * 32 + lid;

    // one expect_tx per CPMB wait, strictly alternating (R8 invariant)
    auto prefetch = [&](int nct, int nb, bool ok) {
        if (!ok) return;
        if (tid == 0) {
            MBARRIER_EXPECT_TX(sb + OFF_CPMB, 65536);
            BULK_G2S(sb + (nb ? OFF_B1H : OFF_B0H), (const char*)g_hi + nct * 32768, 32768, sb + OFF_CPMB);
            BULK_G2S(sb + (nb ? OFF_B1L : OFF_B0L), (const char*)g_lo + nct * 32768, 32768, sb + OFF_CPMB);
        }
    };

    // epilogue: row sums always; col sums for off-diagonal tiles (symmetry)
    auto epi = [&](int b, int erow0, int ecol0, int nct, int nb, bool nok) {
        MBARRIER_WAIT_PARITY(sb + OFF_MB + b * 8, phs[b]);
        phs[b] ^= 1;
        TCGEN05_FENCE_AFTER();
        prefetch(nct, nb, nok);
        int gi = erow0 + row;
        uint32_t d0[32], d1[32];
        TCGEN05_LD_X32(d0, tbase + b * 128 + colh * 64);
        TCGEN05_LD_X32(d1, tbase + b * 128 + colh * 64 + 32);
        TCGEN05_WAIT_LD();
        bool diag = (erow0 == ecol0);
        int jb = ecol0 + colh * 64;
        float e[64];
        #pragma unroll
        for (int c = 0; c < 32; c++) {
            float x;
            asm("ex2.approx.ftz.f32 %0, %1;" : "=f"(x) : "f"(__uint_as_float(d0[c])));
            e[c] = (diag && (jb + c) == gi) ? 0.f : x;
        }
        #pragma unroll
        for (int c = 0; c < 32; c++) {
            float x;
            asm("ex2.approx.ftz.f32 %0, %1;" : "=f"(x) : "f"(__uint_as_float(d1[c])));
            e[32 + c] = (diag && (jb + 32 + c) == gi) ? 0.f : x;
        }
        float S0 = 0.f, S1 = 0.f;
        #pragma unroll
        for (int c = 0; c < 32; c++) { S0 += e[c]; S1 += e[32 + c]; }
        TCGEN05_FENCE_BEFORE();
        atomicAdd(&g_S[gi], S0 + S1);
        if (!diag) {
            // fold: 5 stages; register count halves; ends with lane l owning
            // cols (colh*64 + l) in e[0] and (colh*64 + 32 + l) in e[1]
            #pragma unroll
            for (int st = 0; st < 5; st++) {
                int k = 1 << st;
                int L = 64 >> st;
                int side = (lid >> st) & 1;
                #pragma unroll
                for (int j = 0; j < 64; j++) {
                    if (j < (L >> 1)) {
                        float keep = side ? e[2 * j + 1] : e[2 * j];
                        float give = side ? e[2 * j] : e[2 * j + 1];
                        float recv = __shfl_xor_sync(0xffffffffu, give, k);
                        e[j] = keep + recv;
                    }
                }
            }
            float* scol = (float*)(smc + OFF_SCOL);
            scol[sub * 128 + colh * 64 + lid] = e[0];
            scol[sub * 128 + colh * 64 + 32 + lid] = e[1];
            __syncthreads();
            if (tid < 128) {
                float v = scol[tid] + scol[128 + tid] + scol[256 + tid] + scol[384 + tid];
                atomicAdd(&g_S[ecol0 + tid], v);
            }
        }
    };

    // prologue: load A band, prefetch B(s0)
    {
        const uint4* sH = g_hi + rt * 2048;
        const uint4* sL = g_lo + rt * 2048;
        uint4* dH = (uint4*)(smc + OFF_AHI);
        uint4* dL = (uint4*)(smc + OFF_ALO);
        for (int i = tid; i < 2048; i += 256) { dH[i] = sH[i]; dL[i] = sL[i]; }
        prefetch(ct, s0 & 1, true);
        __syncthreads();
    }

    for (int s = s0; s < s1; s++) {
        int p = s & 1;
        bool nok = (s + 1 < s1);
        int nct = (ct + 1 < 64) ? ct + 1 : rt + 1;   // next tile's column band
        int nb = (s + 1) & 1;
        __syncthreads();   // all warps past epi(s-2); TMEM/scol reuse safe

        if (rt != curA) {  // band change: drain pending epilogue (no prefetch:
                           // B(s) expect already pending; else-branch issues s+1)
            if (pend >= 0) { epi(pend & 1, prow, pcol, 0, 0, false); pend = -1; }
            __syncthreads();
            const uint4* sH = g_hi + rt * 2048;
            const uint4* sL = g_lo + rt * 2048;
            uint4* dH = (uint4*)(smc + OFF_AHI);
            uint4* dL = (uint4*)(smc + OFF_ALO);
            for (int i = tid; i < 2048; i += 256) { dH[i] = sH[i]; dL[i] = sL[i]; }
            curA = rt;
            __syncthreads();
        }

        if (wid == 0) {    // wait bulk-DMA of B(s), then issue MMA chain
            MBARRIER_WAIT_PARITY(sb + OFF_CPMB, cpph);
            cpph ^= 1;
            TCGEN05_FENCE_AFTER();
            if (elect_one()) {
                uint32_t dtm = tbase + p * 128;
                uint64_t aH = MAKE_DESC(sb + OFF_AHI);
                uint64_t aL = MAKE_DESC(sb + OFF_ALO);
                uint64_t bH = MAKE_DESC(sb + (p ? OFF_B1H : OFF_B0H));
                uint64_t bL = MAKE_DESC(sb + (p ? OFF_B1L : OFF_B0L));
                #pragma unroll
                for (int ks = 0; ks < 8; ks++) mma_ss(dtm, aH + KOFF[ks], bH + KOFF[ks], ks > 0);
                #pragma unroll
                for (int ks = 0; ks < 8; ks++) mma_ss(dtm, aH + KOFF[ks], bL + KOFF[ks], 1u);
                #pragma unroll
                for (int ks = 0; ks < 8; ks++) mma_ss(dtm, aL + KOFF[ks], bH + KOFF[ks], 1u);
                TCGEN05_COMMIT(sb + OFF_MB + p * 8);
            }
        }

        // exactly one prefetch(s+1) per iteration
        if (pend >= 0) epi(pend & 1, prow, pcol, nct, nb, nok);
        else           prefetch(nct, nb, nok);
        pend = s; prow = rt * TILE; pcol = ct * TILE;

        // advance triangular walk
        if (ct + 1 < 64) ct++;
        else { rt++; ct = rt; }
    }
    if (pend >= 0) epi(pend & 1, prow, pcol, 0, 0, false);

    __syncthreads();
    if (tid == 0) {
        MBARRIER_INVAL(sb + OFF_MB); MBARRIER_INVAL(sb + OFF_MB + 8);
        MBARRIER_INVAL(sb + OFF_CPMB);
    }
    __syncthreads();
    if (wid == 0) TCGEN05_DEALLOC(tbase, 512);
#endif  // TC_OK
}

__global__ void k_final(float* __restrict__ out) {
    __shared__ float shL[256], shW[256];
    int tid = threadIdx.x;
    float sl = 0.f, sw = 0.f;
    for (int i = tid; i < Nn; i += 256) {
        int L = g_lab[i];
        if (L != 0) {
            float cnt = (float)(g_hist[L] - 1);
            sl += logf(g_S[i]) - (g_P[i] * INV_T) / cnt;
            sw += 1.f;
        }
    }
    shL[tid] = sl; shW[tid] = sw;
    __syncthreads();
    for (int o = 128; o; o >>= 1) {
        if (tid < o) { shL[tid] += shL[tid + o]; shW[tid] += shW[tid + o]; }
        __syncthreads();
    }
    if (tid == 0) out[0] = shL[0] / shW[0];
}

extern "C" void kernel_launch(void* const* d_in, const int* in_sizes, int n_in,
                              void* d_out, int out_size) {
    (void)in_sizes; (void)n_in; (void)out_size;
    const float* feats  = (const float*)d_in[0];
    const int*   labels = (const int*)d_in[1];
    float*       out    = (float*)d_out;

    cudaFuncSetAttribute(k_main_tc, cudaFuncAttributeMaxDynamicSharedMemorySize, SMEM_SZ);

    // k_main_tc is launch #4 (ncu capture slot)
    k_zero<<<32, 256>>>();
    k_prep<<<2048, 256>>>(feats);
    k_lab<<<32, 256>>>(labels);
    k_main_tc<<<NBLK_TC, 256, SMEM_SZ>>>();
    k_csum<<<1024, 256>>>(feats);
    k_dotp<<<32, 256>>>(feats);
    k_final<<<1, 256>>>(out);
}

// round 12
// speedup vs baseline: 1.5049x; 1.0353x over previous
#include <cuda_runtime.h>
#include <cuda_bf16.h>
#include <cstdint>

// SupConLoss: N=8192 embeddings (C=128, L2-normalized), logits = X X^T / T.
// Warp-specialized tcgen05 syrk over the upper triangle (2080 tiles):
// warp 8 issues bulk-DMA + MMA chains; warps 0-7 run the exp epilogue.
// Row sums + (symmetry) column sums per off-diag tile. P via class sums.

#define Nn 8192
#define TILE 128
#define TRI_TILES 2080               // 64*65/2
#define NBLK_TC 148
#define NTHREADS 288                 // 8 worker warps + 1 issuer warp
#define INV_T 14.285714285714285714f
#define PSCALE 4.5398161f            // sqrt(INV_T * log2(e))

#if !defined(__CUDA_ARCH__)
#  define TC_OK 1
#elif defined(__CUDA_ARCH_FEAT_SM103_ALL) || defined(__CUDA_ARCH_FEAT_SM100_ALL) || \
      defined(__CUDA_ARCH_FEAT_SM101_ALL) || defined(__CUDA_ARCH_FAMILY_SPECIFIC__) || \
      defined(__CUDA_ARCH_SPECIFIC__)
#  define TC_OK 1
#else
#  define TC_OK 0
#endif

__device__ uint4 g_hi[Nn * 128 / 8];   // 2 MB blocked SW128-swizzled bf16 tiles
__device__ uint4 g_lo[Nn * 128 / 8];
__device__ float g_S[Nn];
__device__ float g_P[Nn];
__device__ float g_C[4 * 128];
__device__ int   g_lab[Nn];
__device__ int   g_hist[4];

__device__ __forceinline__ uint32_t smem_u32(const void* p) {
    uint32_t a;
    asm("{ .reg .u64 t; cvta.to.shared.u64 t, %1; cvt.u32.u64 %0, t; }" : "=r"(a) : "l"(p));
    return a;
}
__device__ __forceinline__ uint32_t elect_one() {
    uint32_t pred;
    asm volatile("{ .reg .pred p; elect.sync _|p, 0xFFFFFFFF; selp.b32 %0, 1, 0, p; }" : "=r"(pred));
    return pred;
}
#define MBARRIER_INIT(mb, c) \
    asm volatile("mbarrier.init.shared.b64 [%0], %1;" :: "r"((uint32_t)(mb)), "r"((uint32_t)(c)) : "memory")
#define MBARRIER_INVAL(mb) \
    asm volatile("mbarrier.inval.shared.b64 [%0];" :: "r"((uint32_t)(mb)) : "memory")
#define MBARRIER_ARRIVE(mb) \
    asm volatile("mbarrier.arrive.release.cta.shared::cta.b64 _, [%0];" :: "r"((uint32_t)(mb)) : "memory")
#define MBARRIER_EXPECT_TX(mb, bytes) \
    asm volatile("mbarrier.arrive.expect_tx.shared.b64 _, [%0], %1;" \
                 :: "r"((uint32_t)(mb)), "r"((uint32_t)(bytes)) : "memory")
#define MBARRIER_WAIT_PARITY(mb, ph) do {                                          \
    uint32_t _m = (uint32_t)(mb), _p = (uint32_t)(ph), _d;                         \
    asm volatile("{ .reg .pred p; mbarrier.try_wait.parity.acquire.cta.shared::cta.b64 p, [%1], %2; selp.b32 %0, 1, 0, p; }" \
                 : "=r"(_d) : "r"(_m), "r"(_p) : "memory");                        \
    if (!_d) {                                                                     \
        asm volatile("{ .reg .pred P1; WL_%=: mbarrier.try_wait.parity.acquire.cta.shared::cta.b64 P1, [%0], %1, 0x989680; @P1 bra.uni WD_%=; bra.uni WL_%=; WD_%=: }" \
                     :: "r"(_m), "r"(_p) : "memory");                              \
    } } while (0)

#if TC_OK
#define TCGEN05_ALLOC(sa, n) \
    asm volatile("tcgen05.alloc.cta_group::1.sync.aligned.shared::cta.b32 [%0], %1;" \
                 :: "r"((uint32_t)(sa)), "r"((uint32_t)(n)) : "memory")
#define TCGEN05_DEALLOC(t, n) \
    asm volatile("tcgen05.dealloc.cta_group::1.sync.aligned.b32 %0, %1;" :: "r"(t), "r"((uint32_t)(n)))
#define TCGEN05_RELINQ() \
    asm volatile("tcgen05.relinquish_alloc_permit.cta_group::1.sync.aligned;")
#define TCGEN05_COMMIT(mb) \
    asm volatile("tcgen05.commit.cta_group::1.mbarrier::arrive::one.shared::cluster.b64 [%0];" \
                 :: "r"((uint32_t)(mb)) : "memory")
#define TCGEN05_WAIT_LD()      asm volatile("tcgen05.wait::ld.sync.aligned;" ::: "memory")
#define TCGEN05_FENCE_BEFORE() asm volatile("tcgen05.fence::before_thread_sync;" ::: "memory")
#define TCGEN05_FENCE_AFTER()  asm volatile("tcgen05.fence::after_thread_sync;" ::: "memory")
#define TCGEN05_LD_X32(r, a) \
    asm volatile("tcgen05.ld.sync.aligned.32x32b.x32.b32 " \
        "{%0,%1,%2,%3,%4,%5,%6,%7,%8,%9,%10,%11,%12,%13,%14,%15," \
        "%16,%17,%18,%19,%20,%21,%22,%23,%24,%25,%26,%27,%28,%29,%30,%31}, [%32];" \
        : "=r"((r)[0]),"=r"((r)[1]),"=r"((r)[2]),"=r"((r)[3]),"=r"((r)[4]),"=r"((r)[5]),"=r"((r)[6]),"=r"((r)[7]), \
          "=r"((r)[8]),"=r"((r)[9]),"=r"((r)[10]),"=r"((r)[11]),"=r"((r)[12]),"=r"((r)[13]),"=r"((r)[14]),"=r"((r)[15]), \
          "=r"((r)[16]),"=r"((r)[17]),"=r"((r)[18]),"=r"((r)[19]),"=r"((r)[20]),"=r"((r)[21]),"=r"((r)[22]),"=r"((r)[23]), \
          "=r"((r)[24]),"=r"((r)[25]),"=r"((r)[26]),"=r"((r)[27]),"=r"((r)[28]),"=r"((r)[29]),"=r"((r)[30]),"=r"((r)[31]) \
        : "r"(a))
#define BULK_G2S(dst, src, size, mb) \
    asm volatile("cp.async.bulk.shared::cluster.global.mbarrier::complete_tx::bytes [%0], [%1], %2, [%3];" \
                 :: "r"((uint32_t)(dst)), "l"(src), "r"((uint32_t)(size)), "r"((uint32_t)(mb)) : "memory")

static constexpr uint64_t SMEM_DESC_BASE_SW128 =
    (uint64_t(2) << 61) | (uint64_t(1) << 46) | (uint64_t(64) << 32) | (uint64_t(1) << 16);
#define MAKE_DESC(addr) (SMEM_DESC_BASE_SW128 | ((uint64_t)((addr) >> 4) & 0x3FFF))

#define MMA_IDESC 0x08200490u   // F32 d, BF16 a/b, M=128, N=128
static __device__ __forceinline__ void mma_ss(uint32_t d, uint64_t a, uint64_t b, uint32_t en) {
    asm volatile("{ .reg .pred p; setp.ne.u32 p, %4, 0;\n\t"
        "tcgen05.mma.cta_group::1.kind::f16 [%0], %1, %2, %3, {%5,%5,%5,%5}, p; }"
        :: "r"(d), "l"(a), "l"(b), "r"(MMA_IDESC), "r"(en), "r"(0u) : "memory");
}
#endif  // TC_OK

// ---- smem layout, bytes; tile bases 1024-aligned ----
#define OFF_AHI 0
#define OFF_ALO 32768
#define OFF_B0H 65536
#define OFF_B0L 98304
#define OFF_B1H 131072
#define OFF_B1L 163840
#define OFF_TP    196608
#define OFF_FULL0 196624
#define OFF_FULL1 196632
#define OFF_FREE0 196640
#define OFF_FREE1 196648
#define OFF_CPMB  196656
#define SMEM_SZ   196672

__global__ void k_zero() {
    int i = blockIdx.x * 256 + threadIdx.x;
    if (i < Nn) g_S[i] = 0.f;
    if (i < 512) g_C[i] = 0.f;
    if (i < 4) g_hist[i] = 0;
}

// fp32 [B=4,V=2,C=128,HW=1024], PRE-SCALED by sqrt(EX2C) -> bf16 hi/lo,
// blocked SW128 tile format.
__global__ void k_prep(const float* __restrict__ f) {
    int idx = blockIdx.x * 256 + threadIdx.x;   // 524288
    int n = idx & 8191;
    int j = idx >> 13;
    int vb = n >> 10, hw = n & 1023;
    int v = vb >> 2, b = vb & 3;
    const float* base = f + b * 262144 + v * 131072 + hw;
    float x0 = base[(2 * j) * 1024] * PSCALE;
    float x1 = base[(2 * j + 1) * 1024] * PSCALE;
    __nv_bfloat16 h0 = __float2bfloat16(x0);
    __nv_bfloat16 h1 = __float2bfloat16(x1);
    __nv_bfloat16 l0 = __float2bfloat16(x0 - __bfloat162float(h0));
    __nv_bfloat16 l1 = __float2bfloat16(x1 - __bfloat162float(h1));
    uint32_t hp = (uint32_t)__bfloat16_as_ushort(h0) | ((uint32_t)__bfloat16_as_ushort(h1) << 16);
    uint32_t lp = (uint32_t)__bfloat16_as_ushort(l0) | ((uint32_t)__bfloat16_as_ushort(l1) << 16);
    int band = n >> 7, r = n & 127, k = 2 * j;
    int atom = (r >> 3) + (k >> 6) * 16;
    uint32_t byte = atom * 1024 + (r & 7) * 128 + (k & 63) * 2;
    uint32_t sw = byte ^ ((byte >> 3) & 0x70);  // SW128
    uint32_t w = band * 8192 + (sw >> 2);
    ((uint32_t*)g_hi)[w] = hp;
    ((uint32_t*)g_lo)[w] = lp;
}

__global__ void k_lab(const int* __restrict__ labels) {
    int n = blockIdx.x * 256 + threadIdx.x;
    if (n >= Nn) return;
    int vb = n >> 10;
    int v = vb >> 2, b = vb & 3;
    int L = labels[b * 2048 + v * 1024 + (n & 1023)];
    g_lab[n] = L;
    atomicAdd(&g_hist[L], 1);
}

__global__ void k_csum(const float* __restrict__ f) {
    int bid = blockIdx.x;
    int vb = bid >> 7, c = bid & 127;
    int v = vb >> 2, b = vb & 3;
    int tid = threadIdx.x;
    float4 x = ((const float4*)(f + b * 262144 + v * 131072 + c * 1024))[tid];
    int4  l = ((const int4*)(g_lab + vb * 1024))[tid];
    float s[4] = {0.f, 0.f, 0.f, 0.f};
    s[l.x] += x.x; s[l.y] += x.y; s[l.z] += x.z; s[l.w] += x.w;
    #pragma unroll
    for (int q = 0; q < 4; q++) {
        float r = s[q];
        #pragma unroll
        for (int o = 16; o; o >>= 1) r += __shfl_xor_sync(0xffffffffu, r, o);
        if ((tid & 31) == 0 && r != 0.f) atomicAdd(&g_C[q * 128 + c], r);
    }
}

__global__ void k_dotp(const float* __restrict__ f) {
    __shared__ float sC[512];
    int tid = threadIdx.x;
    int n = blockIdx.x * 256 + tid;
    int vb = n >> 10, hw = n & 1023;
    int v = vb >> 2, b = vb & 3;
    ((float2*)sC)[tid] = ((const float2*)g_C)[tid];
    __syncthreads();
    const float* base = f + b * 262144 + v * 131072 + hw;
    const float* C = sC + g_lab[n] * 128;
    float acc = 0.f;
    #pragma unroll 16
    for (int c = 0; c < 128; c++) acc = fmaf(base[c * 1024], C[c], acc);
    g_P[n] = acc - 1.f;
}

// ---- warp-specialized tcgen05 main ----
__global__ __launch_bounds__(NTHREADS, 1) __cluster_dims__(1, 1, 1) void k_main_tc() {
#if TC_OK
    extern __shared__ char smc[];
    uint32_t sb = smem_u32(smc);
    int tid = threadIdx.x, wid = tid >> 5, lid = tid & 31;

    if (wid == 8) TCGEN05_ALLOC(sb + OFF_TP, 512);
    else          TCGEN05_RELINQ();
    __syncthreads();
    uint32_t tbase;
    asm volatile("ld.shared.b32 %0, [%1];" : "=r"(tbase) : "r"(sb + OFF_TP));
    if (tid == 0) {
        MBARRIER_INIT(sb + OFF_FULL0, 1);
        MBARRIER_INIT(sb + OFF_FULL1, 1);
        MBARRIER_INIT(sb + OFF_FREE0, 256);
        MBARRIER_INIT(sb + OFF_FREE1, 256);
        MBARRIER_INIT(sb + OFF_CPMB, 1);
    }
    __syncthreads();

    const uint32_t KOFF[8] = {0, 2, 4, 6, 1024, 1026, 1028, 1030};  // 16B units

    int s0 = (int)(((long long)blockIdx.x * TRI_TILES) / NBLK_TC);
    int s1 = (int)(((long long)(blockIdx.x + 1) * TRI_TILES) / NBLK_TC);
    int rt0 = 0;
    while ((rt0 + 1) * 64 - ((rt0 + 1) * rt0) / 2 <= s0) rt0++;
    int ct0 = rt0 + (s0 - (rt0 * 64 - (rt0 * (rt0 - 1)) / 2));

    if (wid == 8) {
        // ---------------- issuer warp ----------------
        int cp = 0;                    // CPMB parity
        int fr[2] = {0, 0};            // FREE parities
        int fu[2] = {0, 0};            // FULL parities (issuer's own view)
        int rt = rt0, ct = ct0, curA = -1;

        // initial prefetch of B(s0)
        if (elect_one()) {
            MBARRIER_EXPECT_TX(sb + OFF_CPMB, 65536);
            BULK_G2S(sb + ((s0 & 1) ? OFF_B1H : OFF_B0H), (const char*)g_hi + ct * 32768, 32768, sb + OFF_CPMB);
            BULK_G2S(sb + ((s0 & 1) ? OFF_B1L : OFF_B0L), (const char*)g_lo + ct * 32768, 32768, sb + OFF_CPMB);
        }

        for (int s = s0; s < s1; s++) {
            int b = s & 1;
            if (rt != curA) {          // workers reload A then everyone syncs
                asm volatile("bar.sync 0, %0;" :: "n"(NTHREADS) : "memory");
                asm volatile("fence.proxy.async.shared::cta;" ::: "memory");
                curA = rt;
            }
            MBARRIER_WAIT_PARITY(sb + OFF_CPMB, cp);   // B(s) arrived
            cp ^= 1;
            if (s - s0 >= 2) {         // TMEM buf b free (epi(s-2) LDTM done)
                MBARRIER_WAIT_PARITY(sb + (b ? OFF_FREE1 : OFF_FREE0), fr[b]);
                fr[b] ^= 1;
            }
            TCGEN05_FENCE_AFTER();
            if (elect_one()) {
                uint32_t dtm = tbase + b * 128;
                uint64_t aH = MAKE_DESC(sb + OFF_AHI);
                uint64_t aL = MAKE_DESC(sb + OFF_ALO);
                uint64_t bH = MAKE_DESC(sb + (b ? OFF_B1H : OFF_B0H));
                uint64_t bL = MAKE_DESC(sb + (b ? OFF_B1L : OFF_B0L));
                #pragma unroll
                for (int ks = 0; ks < 8; ks++) mma_ss(dtm, aH + KOFF[ks], bH + KOFF[ks], ks > 0);
                #pragma unroll
                for (int ks = 0; ks < 8; ks++) mma_ss(dtm, aH + KOFF[ks], bL + KOFF[ks], 1u);
                #pragma unroll
                for (int ks = 0; ks < 8; ks++) mma_ss(dtm, aL + KOFF[ks], bH + KOFF[ks], 1u);
                TCGEN05_COMMIT(sb + (b ? OFF_FULL1 : OFF_FULL0));
            }
            if (s + 1 < s1) {          // prefetch B(s+1) into buf 1-b
                if (s - s0 >= 1) {     // MMA(s-1) (last reader of buf 1-b) done
                    MBARRIER_WAIT_PARITY(sb + ((1 - b) ? OFF_FULL1 : OFF_FULL0), fu[1 - b]);
                    fu[1 - b] ^= 1;
                }
                int nct = (ct + 1 < 64) ? ct + 1 : rt + 1;
                if (elect_one()) {
                    MBARRIER_EXPECT_TX(sb + OFF_CPMB, 65536);
                    BULK_G2S(sb + ((1 - b) ? OFF_B1H : OFF_B0H), (const char*)g_hi + nct * 32768, 32768, sb + OFF_CPMB);
                    BULK_G2S(sb + ((1 - b) ? OFF_B1L : OFF_B0L), (const char*)g_lo + nct * 32768, 32768, sb + OFF_CPMB);
                }
            }
            if (ct + 1 < 64) ct++; else { rt++; ct = rt; }
        }
    } else {
        // ---------------- worker warps (256 threads) ----------------
        int pf[2] = {0, 0};            // FULL parities (worker view)
        int rt = rt0, ct = ct0, curA = -1;
        int sub = wid & 3, colh = wid >> 2;
        int row = sub * 32 + lid;

        for (int s = s0; s < s1; s++) {
            int b = s & 1;
            if (rt != curA) {          // reload A band, then sync with issuer
                const uint4* sH = g_hi + rt * 2048;
                const uint4* sL = g_lo + rt * 2048;
                uint4* dH = (uint4*)(smc + OFF_AHI);
                uint4* dL = (uint4*)(smc + OFF_ALO);
                for (int i = tid; i < 2048; i += 256) { dH[i] = sH[i]; dL[i] = sL[i]; }
                asm volatile("fence.proxy.async.shared::cta;" ::: "memory");
                asm volatile("bar.sync 0, %0;" :: "n"(NTHREADS) : "memory");
                curA = rt;
            }
            MBARRIER_WAIT_PARITY(sb + (b ? OFF_FULL1 : OFF_FULL0), pf[b]);
            pf[b] ^= 1;
            TCGEN05_FENCE_AFTER();
            uint32_t d0[32], d1[32];
            TCGEN05_LD_X32(d0, tbase + b * 128 + colh * 64);
            TCGEN05_LD_X32(d1, tbase + b * 128 + colh * 64 + 32);
            TCGEN05_WAIT_LD();
            MBARRIER_ARRIVE(sb + (b ? OFF_FREE1 : OFF_FREE0));  // TMEM buf free

            int gi = rt * TILE + row;
            bool diag = (rt == ct);
            int jb = ct * TILE + colh * 64;
            float S = 0.f;
            // block 0: cols [jb, jb+32)
            {
                float e[32];
                #pragma unroll
                for (int c = 0; c < 32; c++) {
                    float x;
                    asm("ex2.approx.ftz.f32 %0, %1;" : "=f"(x) : "f"(__uint_as_float(d0[c])));
                    e[c] = (diag && (jb + c) == gi) ? 0.f : x;
                }
                #pragma unroll
                for (int c = 0; c < 32; c++) S += e[c];
                if (!diag) {
                    #pragma unroll
                    for (int st = 0; st < 5; st++) {
                        int k = 1 << st;
                        int half = 32 >> (st + 1);
                        int side = (lid >> st) & 1;
                        #pragma unroll
                        for (int j = 0; j < 16; j++) {
                            if (j < half) {
                                float keep = side ? e[2 * j + 1] : e[2 * j];
                                float give = side ? e[2 * j] : e[2 * j + 1];
                                float recv = __shfl_xor_sync(0xffffffffu, give, k);
                                e[j] = keep + recv;
                            }
                        }
                    }
                    atomicAdd(&g_S[jb + lid], e[0]);
                }
            }
            // block 1: cols [jb+32, jb+64)
            {
                float e[32];
                #pragma unroll
                for (int c = 0; c < 32; c++) {
                    float x;
                    asm("ex2.approx.ftz.f32 %0, %1;" : "=f"(x) : "f"(__uint_as_float(d1[c])));
                    e[c] = (diag && (jb + 32 + c) == gi) ? 0.f : x;
                }
                #pragma unroll
                for (int c = 0; c < 32; c++) S += e[c];
                if (!diag) {
                    #pragma unroll
                    for (int st = 0; st < 5; st++) {
                        int k = 1 << st;
                        int half = 32 >> (st + 1);
                        int side = (lid >> st) & 1;
                        #pragma unroll
                        for (int j = 0; j < 16; j++) {
                            if (j < half) {
                                float keep = side ? e[2 * j + 1] : e[2 * j];
                                float give = side ? e[2 * j] : e[2 * j + 1];
                                float recv = __shfl_xor_sync(0xffffffffu, give, k);
                                e[j] = keep + recv;
                            }
                        }
                    }
                    atomicAdd(&g_S[jb + 32 + lid], e[0]);
                }
            }
            atomicAdd(&g_S[gi], S);

            if (ct + 1 < 64) ct++; else { rt++; ct = rt; }
        }
    }

    asm volatile("bar.sync 0, %0;" :: "n"(NTHREADS) : "memory");
    if (tid == 0) {
        MBARRIER_INVAL(sb + OFF_FULL0); MBARRIER_INVAL(sb + OFF_FULL1);
        MBARRIER_INVAL(sb + OFF_FREE0); MBARRIER_INVAL(sb + OFF_FREE1);
        MBARRIER_INVAL(sb + OFF_CPMB);
    }
    asm volatile("bar.sync 0, %0;" :: "n"(NTHREADS) : "memory");
    if (wid == 8) TCGEN05_DEALLOC(tbase, 512);
#endif  // TC_OK
}

__global__ void k_final(float* __restrict__ out) {
    __shared__ float shL[256], shW[256];
    int tid = threadIdx.x;
    float sl = 0.f, sw = 0.f;
    for (int i = tid; i < Nn; i += 256) {
        int L = g_lab[i];
        if (L != 0) {
            float cnt = (float)(g_hist[L] - 1);
            sl += logf(g_S[i]) - (g_P[i] * INV_T) / cnt;
            sw += 1.f;
        }
    }
    shL[tid] = sl; shW[tid] = sw;
    __syncthreads();
    for (int o = 128; o; o >>= 1) {
        if (tid < o) { shL[tid] += shL[tid + o]; shW[tid] += shW[tid + o]; }
        __syncthreads();
    }
    if (tid == 0) out[0] = shL[0] / shW[0];
}

extern "C" void kernel_launch(void* const* d_in, const int* in_sizes, int n_in,
                              void* d_out, int out_size) {
    (void)in_sizes; (void)n_in; (void)out_size;
    const float* feats  = (const float*)d_in[0];
    const int*   labels = (const int*)d_in[1];
    float*       out    = (float*)d_out;

    cudaFuncSetAttribute(k_main_tc, cudaFuncAttributeMaxDynamicSharedMemorySize, SMEM_SZ);

    // k_main_tc is launch #4 (ncu capture slot)
    k_zero<<<32, 256>>>();
    k_prep<<<2048, 256>>>(feats);
    k_lab<<<32, 256>>>(labels);
    k_main_tc<<<NBLK_TC, NTHREADS, SMEM_SZ>>>();
    k_csum<<<1024, 256>>>(feats);
    k_dotp<<<32, 256>>>(feats);
    k_final<<<1, 256>>>(out);
}